// round 7
// baseline (speedup 1.0000x reference)
#include <cuda_runtime.h>
#include <cuda_bf16.h>
#include <cstdint>

#define B_  2
#define S_  2048
#define H_  768
#define NH_ 12
#define HD_ 64
#define KB_ 12          // 768 / 64 k-chunks

// Packed hi/lo bf16 projections: [bh][s][128] (cols 0-63 = hi, 64-127 = lo).
// Q pre-scaled by log2(e)/8 so attention scores are already in log2 domain.
__device__ __align__(16) __nv_bfloat16 g_qp[(size_t)B_ * NH_ * S_ * 128];
__device__ __align__(16) __nv_bfloat16 g_kp[(size_t)B_ * NH_ * S_ * 128];
__device__ __align__(16) __nv_bfloat16 g_vp[(size_t)B_ * NH_ * S_ * 128];
// Packed hi/lo bf16 GEMM inputs:
// g_xb: [4096][12][128]  (per 64-k chunk: 64 hi | 64 lo)
// g_wb: [3][768 n][12][128]  (W transposed, per 64-k chunk: hi | lo)
__device__ __align__(16) __nv_bfloat16 g_xb[(size_t)B_ * S_ * KB_ * 128];
__device__ __align__(16) __nv_bfloat16 g_wb[(size_t)3 * H_ * KB_ * 128];

// ============================ PTX helpers ==================================
__device__ __forceinline__ uint32_t smem_u32(const void* p) {
    uint32_t a;
    asm("{ .reg .u64 t; cvta.to.shared.u64 t, %1; cvt.u32.u64 %0, t; }"
        : "=r"(a) : "l"(p));
    return a;
}
__device__ __forceinline__ void cpasync16(uint32_t dst, const void* src) {
    asm volatile("cp.async.cg.shared.global [%0], [%1], 16;"
                 :: "r"(dst), "l"(src) : "memory");
}
#define CP_COMMIT() asm volatile("cp.async.commit_group;" ::: "memory")
#define CP_WAIT0()  asm volatile("cp.async.wait_group 0;" ::: "memory")
#define CP_WAIT1()  asm volatile("cp.async.wait_group 1;" ::: "memory")
#define CP_WAIT2()  asm volatile("cp.async.wait_group 2;" ::: "memory")

__device__ __forceinline__ void ldsm4(uint32_t r[4], uint32_t addr) {
    asm volatile("ldmatrix.sync.aligned.m8n8.x4.shared.b16 {%0,%1,%2,%3}, [%4];"
        : "=r"(r[0]), "=r"(r[1]), "=r"(r[2]), "=r"(r[3]) : "r"(addr));
}
__device__ __forceinline__ void ldsm4t(uint32_t r[4], uint32_t addr) {
    asm volatile("ldmatrix.sync.aligned.m8n8.x4.trans.shared.b16 {%0,%1,%2,%3}, [%4];"
        : "=r"(r[0]), "=r"(r[1]), "=r"(r[2]), "=r"(r[3]) : "r"(addr));
}
__device__ __forceinline__ void mma16816(float c[4], const uint32_t a[4],
                                         uint32_t b0, uint32_t b1) {
    asm volatile("mma.sync.aligned.m16n8k16.row.col.f32.bf16.bf16.f32 "
        "{%0,%1,%2,%3}, {%4,%5,%6,%7}, {%8,%9}, {%0,%1,%2,%3};"
        : "+f"(c[0]), "+f"(c[1]), "+f"(c[2]), "+f"(c[3])
        : "r"(a[0]), "r"(a[1]), "r"(a[2]), "r"(a[3]), "r"(b0), "r"(b1));
}
__device__ __forceinline__ float ex2f(float x) {
    float y; asm("ex2.approx.f32 %0, %1;" : "=f"(y) : "f"(x)); return y;
}
// pack two fp32 -> bf16x2 (first arg in bits [15:0], second in bits [31:16])
__device__ __forceinline__ uint32_t packbf(float lo, float hi) {
    uint32_t r; asm("cvt.rn.bf16x2.f32 %0, %1, %2;" : "=r"(r) : "f"(hi), "f"(lo));
    return r;
}
// smem tile addressing: rows of 128 bf16 = 256B = 16 chunks of 16B,
// chunk XOR-swizzled by (row&7) -> conflict-free ldmatrix.
__device__ __forceinline__ uint32_t swa(int row, int chunk) {
    return (uint32_t)(row * 256 + ((chunk ^ (row & 7)) << 4));
}

// ---------------------------------------------------------------------------
// conv_x: X fp32 [4096][768] -> g_xb packed hi/lo bf16 [m][kb][128].
// ---------------------------------------------------------------------------
__global__ __launch_bounds__(256) void conv_x_kernel(const float* __restrict__ X)
{
    const int t = blockIdx.x * 256 + threadIdx.x;     // 4096*384 threads
    const int m = t / 384, r = t % 384;
    const int kb = r >> 5, pr = r & 31;
    float2 x = *(const float2*)(X + (size_t)m * H_ + kb * 64 + 2 * pr);
    uint32_t hi = packbf(x.x, x.y);
    float r0 = x.x - __uint_as_float(hi << 16);
    float r1 = x.y - __uint_as_float(hi & 0xffff0000u);
    uint32_t lo = packbf(r0, r1);
    uint32_t* dst = (uint32_t*)(g_xb + ((size_t)m * KB_ + kb) * 128);
    dst[pr]      = hi;
    dst[32 + pr] = lo;
}

// ---------------------------------------------------------------------------
// conv_w: W fp32 [768 k][768 n] -> g_wb packed hi/lo bf16 [which][n][kb][128]
// ---------------------------------------------------------------------------
__global__ __launch_bounds__(256) void conv_w_kernel(
    const float* __restrict__ Wq, const float* __restrict__ Wk,
    const float* __restrict__ Wv)
{
    const int kb = blockIdx.x, ng = blockIdx.y, which = blockIdx.z;
    const float* W = (which == 0) ? Wq : (which == 1) ? Wk : Wv;

    __shared__ float T[64][65];
    const int tid = threadIdx.x;
    #pragma unroll
    for (int i = 0; i < 16; i++) {
        int idx = tid + 256 * i;
        int r = idx >> 6, c = idx & 63;
        T[r][c] = W[(size_t)(kb * 64 + r) * H_ + ng * 64 + c];
    }
    __syncthreads();

    const int n  = tid >> 2;
    const int jb = tid & 3;
    uint32_t* dst = (uint32_t*)(g_wb +
        (((size_t)which * H_ + ng * 64 + n) * KB_ + kb) * 128);
    #pragma unroll
    for (int j = 0; j < 8; j++) {
        int k2 = jb * 8 + j;
        float w0 = T[2 * k2][n], w1 = T[2 * k2 + 1][n];
        uint32_t hi = packbf(w0, w1);
        float r0 = w0 - __uint_as_float(hi << 16);
        float r1 = w1 - __uint_as_float(hi & 0xffff0000u);
        dst[k2]      = hi;
        dst[32 + k2] = packbf(r0, r1);
    }
}

// ---------------------------------------------------------------------------
// HMMA QKV GEMM, triple-buffered (prefetch distance 2).
// smem 3 x (32KB A + 32KB B) = 192KB, 1 CTA/SM.
// ---------------------------------------------------------------------------
#define GSM_TOT 196608

__global__ void __launch_bounds__(256, 1) qkv_mma_kernel(
    const float* __restrict__ bq, const float* __restrict__ bk,
    const float* __restrict__ bv)
{
    extern __shared__ char sm[];
    const uint32_t smb = smem_u32(sm);

    const int tid = threadIdx.x;
    const int l = tid & 31, w = tid >> 5;
    const int wm = w & 3, wn = w >> 2;
    const int which = blockIdx.z;
    const int m0 = blockIdx.y * 128;
    const int n0 = blockIdx.x * 128;

    const __nv_bfloat16* Ag = g_xb + (size_t)m0 * KB_ * 128;
    const __nv_bfloat16* Bg = g_wb + ((size_t)which * H_ + n0) * KB_ * 128;

    float s[2][8][4];
    #pragma unroll
    for (int mt = 0; mt < 2; mt++)
        #pragma unroll
        for (int nt = 0; nt < 8; nt++)
            #pragma unroll
            for (int j = 0; j < 4; j++) s[mt][nt][j] = 0.0f;

    const int arow0 = 32 * wm + (l & 15);
    const int achnk = l >> 4;
    const int krow  = 64 * wn + (l & 7) + ((l >> 4) << 3);
    const int kchnk = (l >> 3) & 1;

    // prologue: chunks 0 and 1 into buffers 0 and 1
    #pragma unroll
    for (int pb = 0; pb < 2; pb++) {
        const uint32_t off = (uint32_t)(pb * 65536);
        #pragma unroll
        for (int i = 0; i < 8; i++) {
            int idx = tid + 256 * i;
            int r = idx >> 4, ch = idx & 15;
            uint32_t d = swa(r, ch) + off;
            cpasync16(smb + d,         Ag + ((size_t)r * KB_ + pb) * 128 + ch * 8);
            cpasync16(smb + 32768 + d, Bg + ((size_t)r * KB_ + pb) * 128 + ch * 8);
        }
        CP_COMMIT();
    }

    for (int kb = 0; kb < KB_; kb++) {
        CP_WAIT1();          // chunk kb complete
        __syncthreads();     // all warps past compute(kb-1); buffer (kb+2)%3 free
        if (kb + 2 < KB_) {
            const uint32_t off = (uint32_t)(((kb + 2) % 3) * 65536);
            #pragma unroll
            for (int i = 0; i < 8; i++) {
                int idx = tid + 256 * i;
                int r = idx >> 4, ch = idx & 15;
                uint32_t d = swa(r, ch) + off;
                cpasync16(smb + d,         Ag + ((size_t)r * KB_ + kb + 2) * 128 + ch * 8);
                cpasync16(smb + 32768 + d, Bg + ((size_t)r * KB_ + kb + 2) * 128 + ch * 8);
            }
        }
        CP_COMMIT();

        const uint32_t smA = smb + (uint32_t)((kb % 3) * 65536);
        const uint32_t smB = smA + 32768;

        #pragma unroll
        for (int ks = 0; ks < 4; ks++) {
            uint32_t ah[2][4], al[2][4], bh[4][4], bl[4][4];
            #pragma unroll
            for (int mt = 0; mt < 2; mt++)
                ldsm4(ah[mt], smA + swa(arow0 + 16 * mt, ks * 2 + achnk));
            #pragma unroll
            for (int bt = 0; bt < 4; bt++)
                ldsm4(bh[bt], smB + swa(16 * bt + krow, ks * 2 + kchnk));
            #pragma unroll
            for (int mt = 0; mt < 2; mt++)
                #pragma unroll
                for (int bt = 0; bt < 4; bt++) {
                    mma16816(s[mt][2 * bt],     ah[mt], bh[bt][0], bh[bt][1]);
                    mma16816(s[mt][2 * bt + 1], ah[mt], bh[bt][2], bh[bt][3]);
                }
            #pragma unroll
            for (int bt = 0; bt < 4; bt++)
                ldsm4(bl[bt], smB + swa(16 * bt + krow, 8 + ks * 2 + kchnk));
            #pragma unroll
            for (int mt = 0; mt < 2; mt++)
                #pragma unroll
                for (int bt = 0; bt < 4; bt++) {
                    mma16816(s[mt][2 * bt],     ah[mt], bl[bt][0], bl[bt][1]);
                    mma16816(s[mt][2 * bt + 1], ah[mt], bl[bt][2], bl[bt][3]);
                }
            #pragma unroll
            for (int mt = 0; mt < 2; mt++)
                ldsm4(al[mt], smA + swa(arow0 + 16 * mt, 8 + ks * 2 + achnk));
            #pragma unroll
            for (int mt = 0; mt < 2; mt++)
                #pragma unroll
                for (int bt = 0; bt < 4; bt++) {
                    mma16816(s[mt][2 * bt],     al[mt], bh[bt][0], bh[bt][1]);
                    mma16816(s[mt][2 * bt + 1], al[mt], bh[bt][2], bh[bt][3]);
                }
        }
    }

    // ---- epilogue: +bias, (Q: *log2e/8), hi/lo split, packed store ----
    const float* bias = (which == 0) ? bq : (which == 1) ? bk : bv;
    __nv_bfloat16* Gp = (which == 0) ? g_qp : (which == 1) ? g_kp : g_vp;
    const float sc = (which == 0) ? 0.18033688011112042f : 1.0f;

    const int head = 2 * blockIdx.x + wn;
    #pragma unroll
    for (int mt = 0; mt < 2; mt++) {
        const int r0 = m0 + 32 * wm + 16 * mt + (l >> 2);
        const int b  = r0 >> 11;
        const int s0 = r0 & (S_ - 1);
        const int bh_ = b * NH_ + head;
        uint32_t* d0 = (uint32_t*)(Gp + ((size_t)bh_ * S_ + s0) * 128);
        uint32_t* d1 = (uint32_t*)(Gp + ((size_t)bh_ * S_ + s0 + 8) * 128);
        #pragma unroll
        for (int nt = 0; nt < 8; nt++) {
            const int c0 = 8 * nt + 2 * (l & 3);
            const float b0 = __ldg(bias + head * 64 + c0);
            const float b1 = __ldg(bias + head * 64 + c0 + 1);
            float y00 = (s[mt][nt][0] + b0) * sc;
            float y01 = (s[mt][nt][1] + b1) * sc;
            float y10 = (s[mt][nt][2] + b0) * sc;
            float y11 = (s[mt][nt][3] + b1) * sc;
            uint32_t h0 = packbf(y00, y01);
            uint32_t h1 = packbf(y10, y11);
            uint32_t l0 = packbf(y00 - __uint_as_float(h0 << 16),
                                 y01 - __uint_as_float(h0 & 0xffff0000u));
            uint32_t l1 = packbf(y10 - __uint_as_float(h1 << 16),
                                 y11 - __uint_as_float(h1 & 0xffff0000u));
            d0[c0 >> 1]        = h0;
            d0[32 + (c0 >> 1)] = l0;
            d1[c0 >> 1]        = h1;
            d1[32 + (c0 >> 1)] = l1;
        }
    }
}

// ---------------------------------------------------------------------------
// HMMA flash attention: q-tile 64, kv-tile 32, triple-buffered K/V prefetch,
// Q fragments in registers. smem Q 16KB + 3x16KB = 64KB; 3 CTAs/SM (12 warps).
// ---------------------------------------------------------------------------
#define SMQ   0
#define SMKV  16384
#define SMTOT 65536
#define KVT_  32
#define NT_   (S_ / KVT_)

__global__ void __launch_bounds__(128, 3) attn_kernel(float* __restrict__ out)
{
    extern __shared__ char sm[];
    const uint32_t smb = smem_u32(sm);
    const uint32_t smq = smb + SMQ;

    const int tid = threadIdx.x;
    const int l = tid & 31, w = tid >> 5;
    const int head = blockIdx.y, b = blockIdx.z;
    const int bh = b * NH_ + head;
    const int q0 = blockIdx.x * 64;

    const __nv_bfloat16* Kg0 = g_kp + (size_t)bh * S_ * 128;
    const __nv_bfloat16* Vg0 = g_vp + (size_t)bh * S_ * 128;

    // --- prologue: Q, kv0, kv1 (three cp.async groups) ---
    {
        const __nv_bfloat16* Qg = g_qp + ((size_t)bh * S_ + q0) * 128;
        #pragma unroll
        for (int i = 0; i < 8; i++) {
            int idx = tid + 128 * i;
            int r = idx >> 4, ch = idx & 15;
            cpasync16(smq + swa(r, ch), Qg + (size_t)r * 128 + ch * 8);
        }
        CP_COMMIT();
    }
    #pragma unroll
    for (int pb = 0; pb < 2; pb++) {
        const uint32_t kvb = smb + SMKV + (uint32_t)(pb * 16384);
        const __nv_bfloat16* Kg = Kg0 + (size_t)pb * KVT_ * 128;
        const __nv_bfloat16* Vg = Vg0 + (size_t)pb * KVT_ * 128;
        #pragma unroll
        for (int i = 0; i < 4; i++) {
            int idx = tid + 128 * i;
            int r = idx >> 4, ch = idx & 15;
            uint32_t d = swa(r, ch);
            cpasync16(kvb + d,        Kg + (size_t)r * 128 + ch * 8);
            cpasync16(kvb + 8192 + d, Vg + (size_t)r * 128 + ch * 8);
        }
        CP_COMMIT();
    }

    // fragment lane constants
    const int arow  = (w << 4) + (l & 15);
    const int achnk = l >> 4;
    const int krow  = (l & 7) + ((l >> 4) << 3);
    const int kchnk = (l >> 3) & 1;
    const int vchnk = l >> 4;

    // --- hoist Q fragments (hi/lo) into registers ---
    CP_WAIT2();          // Q group complete
    __syncthreads();
    uint32_t qf[2][4][4];
    #pragma unroll
    for (int hl = 0; hl < 2; hl++)
        #pragma unroll
        for (int ks = 0; ks < 4; ks++)
            ldsm4(qf[hl][ks], smq + swa(arow, hl * 8 + ks * 2 + achnk));

    float o[8][4];
    #pragma unroll
    for (int i = 0; i < 8; i++)
        #pragma unroll
        for (int j = 0; j < 4; j++) o[i][j] = 0.0f;
    float lsum0 = 0.0f, lsum1 = 0.0f;

    for (int t = 0; t < NT_; t++) {
        CP_WAIT1();      // kv tile t resident
        __syncthreads(); // all warps past compute(t-1); buffer (t+2)%3 free
        if (t + 2 < NT_) {
            const uint32_t kvb = smb + SMKV + (uint32_t)(((t + 2) % 3) * 16384);
            const __nv_bfloat16* Kg = Kg0 + (size_t)(t + 2) * KVT_ * 128;
            const __nv_bfloat16* Vg = Vg0 + (size_t)(t + 2) * KVT_ * 128;
            #pragma unroll
            for (int i = 0; i < 4; i++) {
                int idx = tid + 128 * i;
                int r = idx >> 4, ch = idx & 15;
                uint32_t d = swa(r, ch);
                cpasync16(kvb + d,        Kg + (size_t)r * 128 + ch * 8);
                cpasync16(kvb + 8192 + d, Vg + (size_t)r * 128 + ch * 8);
            }
        }
        CP_COMMIT();

        const uint32_t smk = smb + SMKV + (uint32_t)((t % 3) * 16384);
        const uint32_t smv = smk + 8192;

        // ---- S = Qh.Kh + Ql.Kh + Qh.Kl  (Kh loaded once, used twice) ----
        float s[4][4];
        #pragma unroll
        for (int i = 0; i < 4; i++)
            #pragma unroll
            for (int j = 0; j < 4; j++) s[i][j] = 0.0f;

        #pragma unroll
        for (int ks = 0; ks < 4; ks++) {
            #pragma unroll
            for (int np = 0; np < 2; np++) {
                uint32_t kh[4], kl[4];
                ldsm4(kh, smk + swa(np * 16 + krow, ks * 2 + kchnk));
                ldsm4(kl, smk + swa(np * 16 + krow, 8 + ks * 2 + kchnk));
                mma16816(s[2 * np],     qf[0][ks], kh[0], kh[1]);
                mma16816(s[2 * np + 1], qf[0][ks], kh[2], kh[3]);
                mma16816(s[2 * np],     qf[1][ks], kh[0], kh[1]);
                mma16816(s[2 * np + 1], qf[1][ks], kh[2], kh[3]);
                mma16816(s[2 * np],     qf[0][ks], kl[0], kl[1]);
                mma16816(s[2 * np + 1], qf[0][ks], kl[2], kl[3]);
            }
        }

        // ---- exp2, sum, hi/lo split, PV (3-pass) ----
        #pragma unroll
        for (int c = 0; c < 2; c++) {
            uint32_t ah[4], al[4];
            #pragma unroll
            for (int h = 0; h < 2; h++) {
                float* sp = s[2 * c + h];
                float p0 = ex2f(sp[0]), p1 = ex2f(sp[1]);
                float p2 = ex2f(sp[2]), p3 = ex2f(sp[3]);
                lsum0 += p0 + p1;
                lsum1 += p2 + p3;
                uint32_t h01 = packbf(p0, p1);
                uint32_t h23 = packbf(p2, p3);
                float r0 = p0 - __uint_as_float(h01 << 16);
                float r1 = p1 - __uint_as_float(h01 & 0xffff0000u);
                float r2 = p2 - __uint_as_float(h23 << 16);
                float r3 = p3 - __uint_as_float(h23 & 0xffff0000u);
                ah[2 * h]     = h01;
                ah[2 * h + 1] = h23;
                al[2 * h]     = packbf(r0, r1);
                al[2 * h + 1] = packbf(r2, r3);
            }
            const int vrow = c * 16 + (l & 15);
            uint32_t vh[4][4], vl[4][4];
            #pragma unroll
            for (int j = 0; j < 4; j++) {
                ldsm4t(vh[j], smv + swa(vrow, 2 * j + vchnk));
                ldsm4t(vl[j], smv + swa(vrow, 8 + 2 * j + vchnk));
            }
            #pragma unroll
            for (int j = 0; j < 4; j++) {
                mma16816(o[2 * j],     ah, vh[j][0], vh[j][1]);
                mma16816(o[2 * j + 1], ah, vh[j][2], vh[j][3]);
            }
            #pragma unroll
            for (int j = 0; j < 4; j++) {
                mma16816(o[2 * j],     al, vh[j][0], vh[j][1]);
                mma16816(o[2 * j + 1], al, vh[j][2], vh[j][3]);
            }
            #pragma unroll
            for (int j = 0; j < 4; j++) {
                mma16816(o[2 * j],     ah, vl[j][0], vl[j][1]);
                mma16816(o[2 * j + 1], ah, vl[j][2], vl[j][3]);
            }
        }
    }

    // ---- epilogue ----
    lsum0 += __shfl_xor_sync(0xffffffffu, lsum0, 1);
    lsum0 += __shfl_xor_sync(0xffffffffu, lsum0, 2);
    lsum1 += __shfl_xor_sync(0xffffffffu, lsum1, 1);
    lsum1 += __shfl_xor_sync(0xffffffffu, lsum1, 2);
    const float inv0 = 1.0f / lsum0;
    const float inv1 = 1.0f / lsum1;

    const int row0 = q0 + w * 16 + (l >> 2);
    const int row1 = row0 + 8;
    const int colb = head * HD_ + 2 * (l & 3);
    float* out0 = out + ((size_t)b * S_ + row0) * H_ + colb;
    float* out1 = out + ((size_t)b * S_ + row1) * H_ + colb;
    #pragma unroll
    for (int nt = 0; nt < 8; nt++) {
        *(float2*)(out0 + nt * 8) = make_float2(o[nt][0] * inv0, o[nt][1] * inv0);
        *(float2*)(out1 + nt * 8) = make_float2(o[nt][2] * inv1, o[nt][3] * inv1);
    }
}

// ---------------------------------------------------------------------------
extern "C" void kernel_launch(void* const* d_in, const int* in_sizes, int n_in,
                              void* d_out, int out_size)
{
    (void)in_sizes; (void)n_in; (void)out_size;
    const float* X  = (const float*)d_in[0];
    const float* Wq = (const float*)d_in[1];
    const float* bq = (const float*)d_in[2];
    const float* Wk = (const float*)d_in[3];
    const float* bk = (const float*)d_in[4];
    const float* Wv = (const float*)d_in[5];
    const float* bv = (const float*)d_in[6];
    float* out = (float*)d_out;

    cudaFuncSetAttribute(qkv_mma_kernel,
                         cudaFuncAttributeMaxDynamicSharedMemorySize, GSM_TOT);
    cudaFuncSetAttribute(attn_kernel,
                         cudaFuncAttributeMaxDynamicSharedMemorySize, SMTOT);

    conv_x_kernel<<<(B_ * S_ * 384) / 256, 256>>>(X);
    conv_w_kernel<<<dim3(KB_, H_ / 64, 3), 256>>>(Wq, Wk, Wv);
    qkv_mma_kernel<<<dim3(H_ / 128, (B_ * S_) / 128, 3), 256, GSM_TOT>>>(bq, bk, bv);
    attn_kernel<<<dim3(S_ / 64, NH_, B_), 128, SMTOT>>>(out);
}

// round 8
// speedup vs baseline: 1.0264x; 1.0264x over previous
#include <cuda_runtime.h>
#include <cuda_bf16.h>
#include <cstdint>

#define B_  2
#define S_  2048
#define H_  768
#define NH_ 12
#define HD_ 64
#define KB_ 12          // 768 / 64 k-chunks

// Packed hi/lo bf16 projections: [bh][s][128] (cols 0-63 = hi, 64-127 = lo).
// Q pre-scaled by log2(e)/8 so attention scores are already in log2 domain.
__device__ __align__(16) __nv_bfloat16 g_qp[(size_t)B_ * NH_ * S_ * 128];
__device__ __align__(16) __nv_bfloat16 g_kp[(size_t)B_ * NH_ * S_ * 128];
__device__ __align__(16) __nv_bfloat16 g_vp[(size_t)B_ * NH_ * S_ * 128];
// Packed hi/lo bf16 GEMM inputs:
// g_xb: [4096][12][128]  (per 64-k chunk: 64 hi | 64 lo)
// g_wb: [3][768 n][12][128]  (W transposed, per 64-k chunk: hi | lo)
__device__ __align__(16) __nv_bfloat16 g_xb[(size_t)B_ * S_ * KB_ * 128];
__device__ __align__(16) __nv_bfloat16 g_wb[(size_t)3 * H_ * KB_ * 128];

// ============================ PTX helpers ==================================
__device__ __forceinline__ uint32_t smem_u32(const void* p) {
    uint32_t a;
    asm("{ .reg .u64 t; cvta.to.shared.u64 t, %1; cvt.u32.u64 %0, t; }"
        : "=r"(a) : "l"(p));
    return a;
}
__device__ __forceinline__ void cpasync16(uint32_t dst, const void* src) {
    asm volatile("cp.async.cg.shared.global [%0], [%1], 16;"
                 :: "r"(dst), "l"(src) : "memory");
}
#define CP_COMMIT() asm volatile("cp.async.commit_group;" ::: "memory")
#define CP_WAIT0()  asm volatile("cp.async.wait_group 0;" ::: "memory")
#define CP_WAIT1()  asm volatile("cp.async.wait_group 1;" ::: "memory")
#define CP_WAIT2()  asm volatile("cp.async.wait_group 2;" ::: "memory")

__device__ __forceinline__ void ldsm4(uint32_t r[4], uint32_t addr) {
    asm volatile("ldmatrix.sync.aligned.m8n8.x4.shared.b16 {%0,%1,%2,%3}, [%4];"
        : "=r"(r[0]), "=r"(r[1]), "=r"(r[2]), "=r"(r[3]) : "r"(addr));
}
__device__ __forceinline__ void ldsm4t(uint32_t r[4], uint32_t addr) {
    asm volatile("ldmatrix.sync.aligned.m8n8.x4.trans.shared.b16 {%0,%1,%2,%3}, [%4];"
        : "=r"(r[0]), "=r"(r[1]), "=r"(r[2]), "=r"(r[3]) : "r"(addr));
}
__device__ __forceinline__ void mma16816(float c[4], const uint32_t a[4],
                                         uint32_t b0, uint32_t b1) {
    asm volatile("mma.sync.aligned.m16n8k16.row.col.f32.bf16.bf16.f32 "
        "{%0,%1,%2,%3}, {%4,%5,%6,%7}, {%8,%9}, {%0,%1,%2,%3};"
        : "+f"(c[0]), "+f"(c[1]), "+f"(c[2]), "+f"(c[3])
        : "r"(a[0]), "r"(a[1]), "r"(a[2]), "r"(a[3]), "r"(b0), "r"(b1));
}
__device__ __forceinline__ float ex2f(float x) {
    float y; asm("ex2.approx.f32 %0, %1;" : "=f"(y) : "f"(x)); return y;
}
// pack two fp32 -> bf16x2 (first arg in bits [15:0], second in bits [31:16])
__device__ __forceinline__ uint32_t packbf(float lo, float hi) {
    uint32_t r; asm("cvt.rn.bf16x2.f32 %0, %1, %2;" : "=r"(r) : "f"(hi), "f"(lo));
    return r;
}
// smem tile addressing: rows of 128 bf16 = 256B = 16 chunks of 16B,
// chunk XOR-swizzled by (row&7) -> conflict-free ldmatrix.
__device__ __forceinline__ uint32_t swa(int row, int chunk) {
    return (uint32_t)(row * 256 + ((chunk ^ (row & 7)) << 4));
}

// ---------------------------------------------------------------------------
// conv_x: X fp32 [4096][768] -> g_xb packed hi/lo bf16 [m][kb][128].
// ---------------------------------------------------------------------------
__global__ __launch_bounds__(256) void conv_x_kernel(const float* __restrict__ X)
{
    const int t = blockIdx.x * 256 + threadIdx.x;     // 4096*384 threads
    const int m = t / 384, r = t % 384;
    const int kb = r >> 5, pr = r & 31;
    float2 x = *(const float2*)(X + (size_t)m * H_ + kb * 64 + 2 * pr);
    uint32_t hi = packbf(x.x, x.y);
    float r0 = x.x - __uint_as_float(hi << 16);
    float r1 = x.y - __uint_as_float(hi & 0xffff0000u);
    uint32_t lo = packbf(r0, r1);
    uint32_t* dst = (uint32_t*)(g_xb + ((size_t)m * KB_ + kb) * 128);
    dst[pr]      = hi;
    dst[32 + pr] = lo;
}

// ---------------------------------------------------------------------------
// conv_w: W fp32 [768 k][768 n] -> g_wb packed hi/lo bf16 [which][n][kb][128]
// ---------------------------------------------------------------------------
__global__ __launch_bounds__(256) void conv_w_kernel(
    const float* __restrict__ Wq, const float* __restrict__ Wk,
    const float* __restrict__ Wv)
{
    const int kb = blockIdx.x, ng = blockIdx.y, which = blockIdx.z;
    const float* W = (which == 0) ? Wq : (which == 1) ? Wk : Wv;

    __shared__ float T[64][65];
    const int tid = threadIdx.x;
    #pragma unroll
    for (int i = 0; i < 16; i++) {
        int idx = tid + 256 * i;
        int r = idx >> 6, c = idx & 63;
        T[r][c] = W[(size_t)(kb * 64 + r) * H_ + ng * 64 + c];
    }
    __syncthreads();

    const int n  = tid >> 2;
    const int jb = tid & 3;
    uint32_t* dst = (uint32_t*)(g_wb +
        (((size_t)which * H_ + ng * 64 + n) * KB_ + kb) * 128);
    #pragma unroll
    for (int j = 0; j < 8; j++) {
        int k2 = jb * 8 + j;
        float w0 = T[2 * k2][n], w1 = T[2 * k2 + 1][n];
        uint32_t hi = packbf(w0, w1);
        float r0 = w0 - __uint_as_float(hi << 16);
        float r1 = w1 - __uint_as_float(hi & 0xffff0000u);
        dst[k2]      = hi;
        dst[32 + k2] = packbf(r0, r1);
    }
}

// ---------------------------------------------------------------------------
// HMMA QKV GEMM v2: 512 thr (16 warps, 4m x 4n), tile 128m x 256n (4 heads),
// 64-k chunks double-buffered. smem 2 x (A 32KB + B 64KB) = 192KB, 1 CTA/SM.
// ---------------------------------------------------------------------------
#define GSM_TOT 196608
#define GBUF    98304

__global__ void __launch_bounds__(512, 1) qkv_mma_kernel(
    const float* __restrict__ bq, const float* __restrict__ bk,
    const float* __restrict__ bv)
{
    extern __shared__ char sm[];
    const uint32_t smb = smem_u32(sm);

    const int tid = threadIdx.x;
    const int l = tid & 31, w = tid >> 5;
    const int wm = w & 3, wn = w >> 2;           // 4 m-warps x 4 n-warps
    const int which = blockIdx.z;
    const int m0 = blockIdx.y * 128;
    const int n0 = blockIdx.x * 256;

    const __nv_bfloat16* Ag = g_xb + (size_t)m0 * KB_ * 128;
    const __nv_bfloat16* Bg = g_wb + ((size_t)which * H_ + n0) * KB_ * 128;

    float s[2][8][4];
    #pragma unroll
    for (int mt = 0; mt < 2; mt++)
        #pragma unroll
        for (int nt = 0; nt < 8; nt++)
            #pragma unroll
            for (int j = 0; j < 4; j++) s[mt][nt][j] = 0.0f;

    const int arow0 = 32 * wm + (l & 15);
    const int achnk = l >> 4;
    const int krow  = 64 * wn + (l & 7) + ((l >> 4) << 3);
    const int kchnk = (l >> 3) & 1;

    // loader lambda-ish: A tile 128 rows (2048 chunks), B tile 256 rows (4096)
    // prologue: chunk 0 into buffer 0
    {
        #pragma unroll
        for (int i = 0; i < 4; i++) {
            int idx = tid + 512 * i;
            int r = idx >> 4, ch = idx & 15;
            cpasync16(smb + swa(r, ch), Ag + ((size_t)r * KB_) * 128 + ch * 8);
        }
        #pragma unroll
        for (int i = 0; i < 8; i++) {
            int idx = tid + 512 * i;
            int r = idx >> 4, ch = idx & 15;
            cpasync16(smb + 32768 + swa(r, ch), Bg + ((size_t)r * KB_) * 128 + ch * 8);
        }
        CP_COMMIT();
    }

    for (int kb = 0; kb < KB_; kb++) {
        // issue next chunk into the other buffer (freed by the sync at the
        // end of the previous iteration's compute)
        if (kb + 1 < KB_) {
            const uint32_t off = (uint32_t)(((kb + 1) & 1) * GBUF);
            #pragma unroll
            for (int i = 0; i < 4; i++) {
                int idx = tid + 512 * i;
                int r = idx >> 4, ch = idx & 15;
                cpasync16(smb + off + swa(r, ch),
                          Ag + ((size_t)r * KB_ + kb + 1) * 128 + ch * 8);
            }
            #pragma unroll
            for (int i = 0; i < 8; i++) {
                int idx = tid + 512 * i;
                int r = idx >> 4, ch = idx & 15;
                cpasync16(smb + off + 32768 + swa(r, ch),
                          Bg + ((size_t)r * KB_ + kb + 1) * 128 + ch * 8);
            }
            CP_COMMIT();
            CP_WAIT1();      // chunk kb complete
        } else {
            CP_WAIT0();
        }
        __syncthreads();

        const uint32_t smA = smb + (uint32_t)((kb & 1) * GBUF);
        const uint32_t smB = smA + 32768;

        #pragma unroll
        for (int ks = 0; ks < 4; ks++) {
            uint32_t ah[2][4], al[2][4], bb[4][4];
            #pragma unroll
            for (int mt = 0; mt < 2; mt++) {
                ldsm4(ah[mt], smA + swa(arow0 + 16 * mt, ks * 2 + achnk));
                ldsm4(al[mt], smA + swa(arow0 + 16 * mt, 8 + ks * 2 + achnk));
            }
            // B-hi: used by both ah (pass 1) and al (pass 3)
            #pragma unroll
            for (int bt = 0; bt < 4; bt++)
                ldsm4(bb[bt], smB + swa(16 * bt + krow, ks * 2 + kchnk));
            #pragma unroll
            for (int mt = 0; mt < 2; mt++)
                #pragma unroll
                for (int bt = 0; bt < 4; bt++) {
                    mma16816(s[mt][2 * bt],     ah[mt], bb[bt][0], bb[bt][1]);
                    mma16816(s[mt][2 * bt + 1], ah[mt], bb[bt][2], bb[bt][3]);
                }
            #pragma unroll
            for (int mt = 0; mt < 2; mt++)
                #pragma unroll
                for (int bt = 0; bt < 4; bt++) {
                    mma16816(s[mt][2 * bt],     al[mt], bb[bt][0], bb[bt][1]);
                    mma16816(s[mt][2 * bt + 1], al[mt], bb[bt][2], bb[bt][3]);
                }
            // B-lo: replaces B-hi registers
            #pragma unroll
            for (int bt = 0; bt < 4; bt++)
                ldsm4(bb[bt], smB + swa(16 * bt + krow, 8 + ks * 2 + kchnk));
            #pragma unroll
            for (int mt = 0; mt < 2; mt++)
                #pragma unroll
                for (int bt = 0; bt < 4; bt++) {
                    mma16816(s[mt][2 * bt],     ah[mt], bb[bt][0], bb[bt][1]);
                    mma16816(s[mt][2 * bt + 1], ah[mt], bb[bt][2], bb[bt][3]);
                }
        }
        __syncthreads();     // all warps done with buffer kb before overwrite
    }

    // ---- epilogue: +bias, (Q: *log2e/8), hi/lo split, packed store ----
    const float* bias = (which == 0) ? bq : (which == 1) ? bk : bv;
    __nv_bfloat16* Gp = (which == 0) ? g_qp : (which == 1) ? g_kp : g_vp;
    const float sc = (which == 0) ? 0.18033688011112042f : 1.0f;

    const int head = 4 * blockIdx.x + wn;
    #pragma unroll
    for (int mt = 0; mt < 2; mt++) {
        const int r0 = m0 + 32 * wm + 16 * mt + (l >> 2);
        const int b  = r0 >> 11;
        const int s0 = r0 & (S_ - 1);
        const int bh_ = b * NH_ + head;
        uint32_t* d0 = (uint32_t*)(Gp + ((size_t)bh_ * S_ + s0) * 128);
        uint32_t* d1 = (uint32_t*)(Gp + ((size_t)bh_ * S_ + s0 + 8) * 128);
        #pragma unroll
        for (int nt = 0; nt < 8; nt++) {
            const int c0 = 8 * nt + 2 * (l & 3);
            const float b0 = __ldg(bias + head * 64 + c0);
            const float b1 = __ldg(bias + head * 64 + c0 + 1);
            float y00 = (s[mt][nt][0] + b0) * sc;
            float y01 = (s[mt][nt][1] + b1) * sc;
            float y10 = (s[mt][nt][2] + b0) * sc;
            float y11 = (s[mt][nt][3] + b1) * sc;
            uint32_t h0 = packbf(y00, y01);
            uint32_t h1 = packbf(y10, y11);
            uint32_t l0 = packbf(y00 - __uint_as_float(h0 << 16),
                                 y01 - __uint_as_float(h0 & 0xffff0000u));
            uint32_t l1 = packbf(y10 - __uint_as_float(h1 << 16),
                                 y11 - __uint_as_float(h1 & 0xffff0000u));
            d0[c0 >> 1]        = h0;
            d0[32 + (c0 >> 1)] = l0;
            d1[c0 >> 1]        = h1;
            d1[32 + (c0 >> 1)] = l1;
        }
    }
}

// ---------------------------------------------------------------------------
// HMMA flash attention (Round-6 best config): q-tile 64, kv-tile 64,
// triple-buffered K/V prefetch, Q fragments in registers.
// smem Q 16KB + 3x32KB = 112KB; 2 CTAs/SM.
// ---------------------------------------------------------------------------
#define SMQ   0
#define SMKV  16384
#define SMTOT 114688
#define NT_   (S_ / 64)

__global__ void __launch_bounds__(128, 2) attn_kernel(float* __restrict__ out)
{
    extern __shared__ char sm[];
    const uint32_t smb = smem_u32(sm);
    const uint32_t smq = smb + SMQ;

    const int tid = threadIdx.x;
    const int l = tid & 31, w = tid >> 5;
    const int head = blockIdx.y, b = blockIdx.z;
    const int bh = b * NH_ + head;
    const int q0 = blockIdx.x * 64;

    const __nv_bfloat16* Kg0 = g_kp + (size_t)bh * S_ * 128;
    const __nv_bfloat16* Vg0 = g_vp + (size_t)bh * S_ * 128;

    // --- prologue: Q, kv0, kv1 (three cp.async groups) ---
    {
        const __nv_bfloat16* Qg = g_qp + ((size_t)bh * S_ + q0) * 128;
        #pragma unroll
        for (int i = 0; i < 8; i++) {
            int idx = tid + 128 * i;
            int r = idx >> 4, ch = idx & 15;
            cpasync16(smq + swa(r, ch), Qg + (size_t)r * 128 + ch * 8);
        }
        CP_COMMIT();
    }
    #pragma unroll
    for (int pb = 0; pb < 2; pb++) {
        const uint32_t kvb = smb + SMKV + (uint32_t)(pb * 32768);
        const __nv_bfloat16* Kg = Kg0 + (size_t)pb * 64 * 128;
        const __nv_bfloat16* Vg = Vg0 + (size_t)pb * 64 * 128;
        #pragma unroll
        for (int i = 0; i < 8; i++) {
            int idx = tid + 128 * i;
            int r = idx >> 4, ch = idx & 15;
            uint32_t d = swa(r, ch);
            cpasync16(kvb + d,         Kg + (size_t)r * 128 + ch * 8);
            cpasync16(kvb + 16384 + d, Vg + (size_t)r * 128 + ch * 8);
        }
        CP_COMMIT();
    }

    // fragment lane constants
    const int arow  = (w << 4) + (l & 15);
    const int achnk = l >> 4;
    const int krow  = (l & 7) + ((l >> 4) << 3);
    const int kchnk = (l >> 3) & 1;
    const int vchnk = l >> 4;

    // --- hoist Q fragments (hi/lo) into registers ---
    CP_WAIT2();
    __syncthreads();
    uint32_t qf[2][4][4];
    #pragma unroll
    for (int hl = 0; hl < 2; hl++)
        #pragma unroll
        for (int ks = 0; ks < 4; ks++)
            ldsm4(qf[hl][ks], smq + swa(arow, hl * 8 + ks * 2 + achnk));

    float o[8][4];
    #pragma unroll
    for (int i = 0; i < 8; i++)
        #pragma unroll
        for (int j = 0; j < 4; j++) o[i][j] = 0.0f;
    float lsum0 = 0.0f, lsum1 = 0.0f;

    for (int t = 0; t < NT_; t++) {
        CP_WAIT1();
        __syncthreads();
        if (t + 2 < NT_) {
            const uint32_t kvb = smb + SMKV + (uint32_t)(((t + 2) % 3) * 32768);
            const __nv_bfloat16* Kg = Kg0 + (size_t)(t + 2) * 64 * 128;
            const __nv_bfloat16* Vg = Vg0 + (size_t)(t + 2) * 64 * 128;
            #pragma unroll
            for (int i = 0; i < 8; i++) {
                int idx = tid + 128 * i;
                int r = idx >> 4, ch = idx & 15;
                uint32_t d = swa(r, ch);
                cpasync16(kvb + d,         Kg + (size_t)r * 128 + ch * 8);
                cpasync16(kvb + 16384 + d, Vg + (size_t)r * 128 + ch * 8);
            }
        }
        CP_COMMIT();

        const uint32_t smk = smb + SMKV + (uint32_t)((t % 3) * 32768);
        const uint32_t smv = smk + 16384;

        // ---- S = Qh.Kh + Ql.Kh + Qh.Kl ----
        float s[8][4];
        #pragma unroll
        for (int i = 0; i < 8; i++)
            #pragma unroll
            for (int j = 0; j < 4; j++) s[i][j] = 0.0f;

        #pragma unroll
        for (int ks = 0; ks < 4; ks++) {
            #pragma unroll
            for (int np = 0; np < 4; np++) {
                uint32_t kh[4], kl[4];
                ldsm4(kh, smk + swa(np * 16 + krow, ks * 2 + kchnk));
                ldsm4(kl, smk + swa(np * 16 + krow, 8 + ks * 2 + kchnk));
                mma16816(s[2 * np],     qf[0][ks], kh[0], kh[1]);
                mma16816(s[2 * np + 1], qf[0][ks], kh[2], kh[3]);
                mma16816(s[2 * np],     qf[1][ks], kh[0], kh[1]);
                mma16816(s[2 * np + 1], qf[1][ks], kh[2], kh[3]);
                mma16816(s[2 * np],     qf[0][ks], kl[0], kl[1]);
                mma16816(s[2 * np + 1], qf[0][ks], kl[2], kl[3]);
            }
        }

        // ---- exp2, sum, hi/lo split, PV (3-pass) ----
        #pragma unroll
        for (int c = 0; c < 4; c++) {
            uint32_t ah[4], al[4];
            #pragma unroll
            for (int h = 0; h < 2; h++) {
                float* sp = s[2 * c + h];
                float p0 = ex2f(sp[0]), p1 = ex2f(sp[1]);
                float p2 = ex2f(sp[2]), p3 = ex2f(sp[3]);
                lsum0 += p0 + p1;
                lsum1 += p2 + p3;
                uint32_t h01 = packbf(p0, p1);
                uint32_t h23 = packbf(p2, p3);
                float r0 = p0 - __uint_as_float(h01 << 16);
                float r1 = p1 - __uint_as_float(h01 & 0xffff0000u);
                float r2 = p2 - __uint_as_float(h23 << 16);
                float r3 = p3 - __uint_as_float(h23 & 0xffff0000u);
                ah[2 * h]     = h01;
                ah[2 * h + 1] = h23;
                al[2 * h]     = packbf(r0, r1);
                al[2 * h + 1] = packbf(r2, r3);
            }
            const int vrow = c * 16 + (l & 15);
            uint32_t vh[4][4], vl[4][4];
            #pragma unroll
            for (int j = 0; j < 4; j++) {
                ldsm4t(vh[j], smv + swa(vrow, 2 * j + vchnk));
                ldsm4t(vl[j], smv + swa(vrow, 8 + 2 * j + vchnk));
            }
            #pragma unroll
            for (int j = 0; j < 4; j++) {
                mma16816(o[2 * j],     ah, vh[j][0], vh[j][1]);
                mma16816(o[2 * j + 1], ah, vh[j][2], vh[j][3]);
            }
            #pragma unroll
            for (int j = 0; j < 4; j++) {
                mma16816(o[2 * j],     al, vh[j][0], vh[j][1]);
                mma16816(o[2 * j + 1], al, vh[j][2], vh[j][3]);
            }
            #pragma unroll
            for (int j = 0; j < 4; j++) {
                mma16816(o[2 * j],     ah, vl[j][0], vl[j][1]);
                mma16816(o[2 * j + 1], ah, vl[j][2], vl[j][3]);
            }
        }
    }

    // ---- epilogue ----
    lsum0 += __shfl_xor_sync(0xffffffffu, lsum0, 1);
    lsum0 += __shfl_xor_sync(0xffffffffu, lsum0, 2);
    lsum1 += __shfl_xor_sync(0xffffffffu, lsum1, 1);
    lsum1 += __shfl_xor_sync(0xffffffffu, lsum1, 2);
    const float inv0 = 1.0f / lsum0;
    const float inv1 = 1.0f / lsum1;

    const int row0 = q0 + w * 16 + (l >> 2);
    const int row1 = row0 + 8;
    const int colb = head * HD_ + 2 * (l & 3);
    float* out0 = out + ((size_t)b * S_ + row0) * H_ + colb;
    float* out1 = out + ((size_t)b * S_ + row1) * H_ + colb;
    #pragma unroll
    for (int nt = 0; nt < 8; nt++) {
        *(float2*)(out0 + nt * 8) = make_float2(o[nt][0] * inv0, o[nt][1] * inv0);
        *(float2*)(out1 + nt * 8) = make_float2(o[nt][2] * inv1, o[nt][3] * inv1);
    }
}

// ---------------------------------------------------------------------------
extern "C" void kernel_launch(void* const* d_in, const int* in_sizes, int n_in,
                              void* d_out, int out_size)
{
    (void)in_sizes; (void)n_in; (void)out_size;
    const float* X  = (const float*)d_in[0];
    const float* Wq = (const float*)d_in[1];
    const float* bq = (const float*)d_in[2];
    const float* Wk = (const float*)d_in[3];
    const float* bk = (const float*)d_in[4];
    const float* Wv = (const float*)d_in[5];
    const float* bv = (const float*)d_in[6];
    float* out = (float*)d_out;

    cudaFuncSetAttribute(qkv_mma_kernel,
                         cudaFuncAttributeMaxDynamicSharedMemorySize, GSM_TOT);
    cudaFuncSetAttribute(attn_kernel,
                         cudaFuncAttributeMaxDynamicSharedMemorySize, SMTOT);

    conv_x_kernel<<<(B_ * S_ * 384) / 256, 256>>>(X);
    conv_w_kernel<<<dim3(KB_, H_ / 64, 3), 256>>>(Wq, Wk, Wv);
    qkv_mma_kernel<<<dim3(H_ / 256, (B_ * S_) / 128, 3), 512, GSM_TOT>>>(bq, bk, bv);
    attn_kernel<<<dim3(S_ / 64, NH_, B_), 128, SMTOT>>>(out);
}

// round 9
// speedup vs baseline: 1.7061x; 1.6623x over previous
#include <cuda_runtime.h>
#include <cuda_bf16.h>
#include <cuda_fp16.h>
#include <cstdint>

#define B_  2
#define S_  2048
#define H_  768
#define NH_ 12
#define HD_ 64
#define KB_ 12          // 768 / 64 k-chunks

// fp16 projections: [bh][s][64]. Q pre-scaled by log2(e)/8.
__device__ __align__(16) __half g_qh[(size_t)B_ * NH_ * S_ * 64];
__device__ __align__(16) __half g_kh[(size_t)B_ * NH_ * S_ * 64];
__device__ __align__(16) __half g_vh[(size_t)B_ * NH_ * S_ * 64];
// Packed hi/lo bf16 GEMM inputs (GEMM stays bf16 3-pass internally):
__device__ __align__(16) __nv_bfloat16 g_xb[(size_t)B_ * S_ * KB_ * 128];
__device__ __align__(16) __nv_bfloat16 g_wb[(size_t)3 * H_ * KB_ * 128];

// ============================ PTX helpers ==================================
__device__ __forceinline__ uint32_t smem_u32(const void* p) {
    uint32_t a;
    asm("{ .reg .u64 t; cvta.to.shared.u64 t, %1; cvt.u32.u64 %0, t; }"
        : "=r"(a) : "l"(p));
    return a;
}
__device__ __forceinline__ void cpasync16(uint32_t dst, const void* src) {
    asm volatile("cp.async.cg.shared.global [%0], [%1], 16;"
                 :: "r"(dst), "l"(src) : "memory");
}
#define CP_COMMIT() asm volatile("cp.async.commit_group;" ::: "memory")
#define CP_WAIT0()  asm volatile("cp.async.wait_group 0;" ::: "memory")
#define CP_WAIT1()  asm volatile("cp.async.wait_group 1;" ::: "memory")
#define CP_WAIT2()  asm volatile("cp.async.wait_group 2;" ::: "memory")

__device__ __forceinline__ void ldsm4(uint32_t r[4], uint32_t addr) {
    asm volatile("ldmatrix.sync.aligned.m8n8.x4.shared.b16 {%0,%1,%2,%3}, [%4];"
        : "=r"(r[0]), "=r"(r[1]), "=r"(r[2]), "=r"(r[3]) : "r"(addr));
}
__device__ __forceinline__ void ldsm4t(uint32_t r[4], uint32_t addr) {
    asm volatile("ldmatrix.sync.aligned.m8n8.x4.trans.shared.b16 {%0,%1,%2,%3}, [%4];"
        : "=r"(r[0]), "=r"(r[1]), "=r"(r[2]), "=r"(r[3]) : "r"(addr));
}
// bf16 MMA (QKV GEMM)
__device__ __forceinline__ void mma16816(float c[4], const uint32_t a[4],
                                         uint32_t b0, uint32_t b1) {
    asm volatile("mma.sync.aligned.m16n8k16.row.col.f32.bf16.bf16.f32 "
        "{%0,%1,%2,%3}, {%4,%5,%6,%7}, {%8,%9}, {%0,%1,%2,%3};"
        : "+f"(c[0]), "+f"(c[1]), "+f"(c[2]), "+f"(c[3])
        : "r"(a[0]), "r"(a[1]), "r"(a[2]), "r"(a[3]), "r"(b0), "r"(b1));
}
// fp16 MMA (attention)
__device__ __forceinline__ void mma16816h(float c[4], const uint32_t a[4],
                                          uint32_t b0, uint32_t b1) {
    asm volatile("mma.sync.aligned.m16n8k16.row.col.f32.f16.f16.f32 "
        "{%0,%1,%2,%3}, {%4,%5,%6,%7}, {%8,%9}, {%0,%1,%2,%3};"
        : "+f"(c[0]), "+f"(c[1]), "+f"(c[2]), "+f"(c[3])
        : "r"(a[0]), "r"(a[1]), "r"(a[2]), "r"(a[3]), "r"(b0), "r"(b1));
}
__device__ __forceinline__ float ex2f(float x) {
    float y; asm("ex2.approx.f32 %0, %1;" : "=f"(y) : "f"(x)); return y;
}
// pack two fp32 -> bf16x2 / f16x2 (first arg -> bits [15:0])
__device__ __forceinline__ uint32_t packbf(float lo, float hi) {
    uint32_t r; asm("cvt.rn.bf16x2.f32 %0, %1, %2;" : "=r"(r) : "f"(hi), "f"(lo));
    return r;
}
__device__ __forceinline__ uint32_t packh(float lo, float hi) {
    uint32_t r; asm("cvt.rn.f16x2.f32 %0, %1, %2;" : "=r"(r) : "f"(hi), "f"(lo));
    return r;
}
// 256B rows (128 bf16), 16 chunks, XOR swizzle
__device__ __forceinline__ uint32_t swa(int row, int chunk) {
    return (uint32_t)(row * 256 + ((chunk ^ (row & 7)) << 4));
}
// 128B rows (64 fp16), 8 chunks, XOR swizzle
__device__ __forceinline__ uint32_t swa8(int row, int chunk) {
    return (uint32_t)(row * 128 + ((chunk ^ (row & 7)) << 4));
}

// ---------------------------------------------------------------------------
// conv_x: X fp32 [4096][768] -> g_xb packed hi/lo bf16 [m][kb][128].
// ---------------------------------------------------------------------------
__global__ __launch_bounds__(256) void conv_x_kernel(const float* __restrict__ X)
{
    const int t = blockIdx.x * 256 + threadIdx.x;
    const int m = t / 384, r = t % 384;
    const int kb = r >> 5, pr = r & 31;
    float2 x = *(const float2*)(X + (size_t)m * H_ + kb * 64 + 2 * pr);
    uint32_t hi = packbf(x.x, x.y);
    float r0 = x.x - __uint_as_float(hi << 16);
    float r1 = x.y - __uint_as_float(hi & 0xffff0000u);
    uint32_t lo = packbf(r0, r1);
    uint32_t* dst = (uint32_t*)(g_xb + ((size_t)m * KB_ + kb) * 128);
    dst[pr]      = hi;
    dst[32 + pr] = lo;
}

// ---------------------------------------------------------------------------
// conv_w: W fp32 -> g_wb packed hi/lo bf16 [which][n][kb][128] (transposed).
// ---------------------------------------------------------------------------
__global__ __launch_bounds__(256) void conv_w_kernel(
    const float* __restrict__ Wq, const float* __restrict__ Wk,
    const float* __restrict__ Wv)
{
    const int kb = blockIdx.x, ng = blockIdx.y, which = blockIdx.z;
    const float* W = (which == 0) ? Wq : (which == 1) ? Wk : Wv;

    __shared__ float T[64][65];
    const int tid = threadIdx.x;
    #pragma unroll
    for (int i = 0; i < 16; i++) {
        int idx = tid + 256 * i;
        int r = idx >> 6, c = idx & 63;
        T[r][c] = W[(size_t)(kb * 64 + r) * H_ + ng * 64 + c];
    }
    __syncthreads();

    const int n  = tid >> 2;
    const int jb = tid & 3;
    uint32_t* dst = (uint32_t*)(g_wb +
        (((size_t)which * H_ + ng * 64 + n) * KB_ + kb) * 128);
    #pragma unroll
    for (int j = 0; j < 8; j++) {
        int k2 = jb * 8 + j;
        float w0 = T[2 * k2][n], w1 = T[2 * k2 + 1][n];
        uint32_t hi = packbf(w0, w1);
        float r0 = w0 - __uint_as_float(hi << 16);
        float r1 = w1 - __uint_as_float(hi & 0xffff0000u);
        dst[k2]      = hi;
        dst[32 + k2] = packbf(r0, r1);
    }
}

// ---------------------------------------------------------------------------
// HMMA QKV GEMM: 512 thr (16 warps, 4m x 4n), tile 128m x 256n (4 heads),
// bf16 hi/lo 3-term, double-buffered. Epilogue emits fp16 [bh][s][64].
// ---------------------------------------------------------------------------
#define GSM_TOT 196608
#define GBUF    98304

__global__ void __launch_bounds__(512, 1) qkv_mma_kernel(
    const float* __restrict__ bq, const float* __restrict__ bk,
    const float* __restrict__ bv)
{
    extern __shared__ char sm[];
    const uint32_t smb = smem_u32(sm);

    const int tid = threadIdx.x;
    const int l = tid & 31, w = tid >> 5;
    const int wm = w & 3, wn = w >> 2;
    const int which = blockIdx.z;
    const int m0 = blockIdx.y * 128;
    const int n0 = blockIdx.x * 256;

    const __nv_bfloat16* Ag = g_xb + (size_t)m0 * KB_ * 128;
    const __nv_bfloat16* Bg = g_wb + ((size_t)which * H_ + n0) * KB_ * 128;

    float s[2][8][4];
    #pragma unroll
    for (int mt = 0; mt < 2; mt++)
        #pragma unroll
        for (int nt = 0; nt < 8; nt++)
            #pragma unroll
            for (int j = 0; j < 4; j++) s[mt][nt][j] = 0.0f;

    const int arow0 = 32 * wm + (l & 15);
    const int achnk = l >> 4;
    const int krow  = 64 * wn + (l & 7) + ((l >> 4) << 3);
    const int kchnk = (l >> 3) & 1;

    // prologue: chunk 0 into buffer 0
    {
        #pragma unroll
        for (int i = 0; i < 4; i++) {
            int idx = tid + 512 * i;
            int r = idx >> 4, ch = idx & 15;
            cpasync16(smb + swa(r, ch), Ag + ((size_t)r * KB_) * 128 + ch * 8);
        }
        #pragma unroll
        for (int i = 0; i < 8; i++) {
            int idx = tid + 512 * i;
            int r = idx >> 4, ch = idx & 15;
            cpasync16(smb + 32768 + swa(r, ch), Bg + ((size_t)r * KB_) * 128 + ch * 8);
        }
        CP_COMMIT();
    }

    for (int kb = 0; kb < KB_; kb++) {
        if (kb + 1 < KB_) {
            const uint32_t off = (uint32_t)(((kb + 1) & 1) * GBUF);
            #pragma unroll
            for (int i = 0; i < 4; i++) {
                int idx = tid + 512 * i;
                int r = idx >> 4, ch = idx & 15;
                cpasync16(smb + off + swa(r, ch),
                          Ag + ((size_t)r * KB_ + kb + 1) * 128 + ch * 8);
            }
            #pragma unroll
            for (int i = 0; i < 8; i++) {
                int idx = tid + 512 * i;
                int r = idx >> 4, ch = idx & 15;
                cpasync16(smb + off + 32768 + swa(r, ch),
                          Bg + ((size_t)r * KB_ + kb + 1) * 128 + ch * 8);
            }
            CP_COMMIT();
            CP_WAIT1();
        } else {
            CP_WAIT0();
        }
        __syncthreads();

        const uint32_t smA = smb + (uint32_t)((kb & 1) * GBUF);
        const uint32_t smB = smA + 32768;

        #pragma unroll
        for (int ks = 0; ks < 4; ks++) {
            uint32_t ah[2][4], al[2][4], bb[4][4];
            #pragma unroll
            for (int mt = 0; mt < 2; mt++) {
                ldsm4(ah[mt], smA + swa(arow0 + 16 * mt, ks * 2 + achnk));
                ldsm4(al[mt], smA + swa(arow0 + 16 * mt, 8 + ks * 2 + achnk));
            }
            #pragma unroll
            for (int bt = 0; bt < 4; bt++)
                ldsm4(bb[bt], smB + swa(16 * bt + krow, ks * 2 + kchnk));
            #pragma unroll
            for (int mt = 0; mt < 2; mt++)
                #pragma unroll
                for (int bt = 0; bt < 4; bt++) {
                    mma16816(s[mt][2 * bt],     ah[mt], bb[bt][0], bb[bt][1]);
                    mma16816(s[mt][2 * bt + 1], ah[mt], bb[bt][2], bb[bt][3]);
                }
            #pragma unroll
            for (int mt = 0; mt < 2; mt++)
                #pragma unroll
                for (int bt = 0; bt < 4; bt++) {
                    mma16816(s[mt][2 * bt],     al[mt], bb[bt][0], bb[bt][1]);
                    mma16816(s[mt][2 * bt + 1], al[mt], bb[bt][2], bb[bt][3]);
                }
            #pragma unroll
            for (int bt = 0; bt < 4; bt++)
                ldsm4(bb[bt], smB + swa(16 * bt + krow, 8 + ks * 2 + kchnk));
            #pragma unroll
            for (int mt = 0; mt < 2; mt++)
                #pragma unroll
                for (int bt = 0; bt < 4; bt++) {
                    mma16816(s[mt][2 * bt],     ah[mt], bb[bt][0], bb[bt][1]);
                    mma16816(s[mt][2 * bt + 1], ah[mt], bb[bt][2], bb[bt][3]);
                }
        }
        __syncthreads();
    }

    // ---- epilogue: +bias, (Q: *log2e/8), fp16 pack, store [bh][s][64] ----
    const float* bias = (which == 0) ? bq : (which == 1) ? bk : bv;
    __half* Gp = (which == 0) ? g_qh : (which == 1) ? g_kh : g_vh;
    const float sc = (which == 0) ? 0.18033688011112042f : 1.0f;

    const int head = 4 * blockIdx.x + wn;
    #pragma unroll
    for (int mt = 0; mt < 2; mt++) {
        const int r0 = m0 + 32 * wm + 16 * mt + (l >> 2);
        const int b  = r0 >> 11;
        const int s0 = r0 & (S_ - 1);
        const int bh_ = b * NH_ + head;
        uint32_t* d0 = (uint32_t*)(Gp + ((size_t)bh_ * S_ + s0) * 64);
        uint32_t* d1 = (uint32_t*)(Gp + ((size_t)bh_ * S_ + s0 + 8) * 64);
        #pragma unroll
        for (int nt = 0; nt < 8; nt++) {
            const int c0 = 8 * nt + 2 * (l & 3);
            const float b0 = __ldg(bias + head * 64 + c0);
            const float b1 = __ldg(bias + head * 64 + c0 + 1);
            d0[c0 >> 1] = packh((s[mt][nt][0] + b0) * sc, (s[mt][nt][1] + b1) * sc);
            d1[c0 >> 1] = packh((s[mt][nt][2] + b0) * sc, (s[mt][nt][3] + b1) * sc);
        }
    }
}

// ---------------------------------------------------------------------------
// fp16 HMMA flash attention, single-pass QK and PV, no-max softmax.
// q-tile 64, kv-tile 64, triple-buffered prefetch, Q frags in registers.
// smem: Q 8KB + 3 x (K 8KB + V 8KB) = 56KB; 3 CTAs/SM.
// ---------------------------------------------------------------------------
#define SMQ   0
#define SMKV  8192
#define SMTOT 57344
#define NT_   (S_ / 64)

__global__ void __launch_bounds__(128, 3) attn_kernel(float* __restrict__ out)
{
    extern __shared__ char sm[];
    const uint32_t smb = smem_u32(sm);
    const uint32_t smq = smb + SMQ;

    const int tid = threadIdx.x;
    const int l = tid & 31, w = tid >> 5;
    const int head = blockIdx.y, b = blockIdx.z;
    const int bh = b * NH_ + head;
    const int q0 = blockIdx.x * 64;

    const __half* Kg0 = g_kh + (size_t)bh * S_ * 64;
    const __half* Vg0 = g_vh + (size_t)bh * S_ * 64;

    // --- prologue: Q, kv0, kv1 (three cp.async groups) ---
    {
        const __half* Qg = g_qh + ((size_t)bh * S_ + q0) * 64;
        #pragma unroll
        for (int i = 0; i < 4; i++) {
            int idx = tid + 128 * i;
            int r = idx >> 3, ch = idx & 7;
            cpasync16(smq + swa8(r, ch), Qg + (size_t)r * 64 + ch * 8);
        }
        CP_COMMIT();
    }
    #pragma unroll
    for (int pb = 0; pb < 2; pb++) {
        const uint32_t kvb = smb + SMKV + (uint32_t)(pb * 16384);
        const __half* Kg = Kg0 + (size_t)pb * 64 * 64;
        const __half* Vg = Vg0 + (size_t)pb * 64 * 64;
        #pragma unroll
        for (int i = 0; i < 4; i++) {
            int idx = tid + 128 * i;
            int r = idx >> 3, ch = idx & 7;
            uint32_t d = swa8(r, ch);
            cpasync16(kvb + d,        Kg + (size_t)r * 64 + ch * 8);
            cpasync16(kvb + 8192 + d, Vg + (size_t)r * 64 + ch * 8);
        }
        CP_COMMIT();
    }

    // fragment lane constants
    const int arow  = (w << 4) + (l & 15);
    const int achnk = l >> 4;
    const int krow  = (l & 7) + ((l >> 4) << 3);
    const int kchnk = (l >> 3) & 1;
    const int vchnk = l >> 4;

    // --- hoist Q fragments into registers ---
    CP_WAIT2();
    __syncthreads();
    uint32_t qf[4][4];
    #pragma unroll
    for (int ks = 0; ks < 4; ks++)
        ldsm4(qf[ks], smq + swa8(arow, ks * 2 + achnk));

    float o[8][4];
    #pragma unroll
    for (int i = 0; i < 8; i++)
        #pragma unroll
        for (int j = 0; j < 4; j++) o[i][j] = 0.0f;
    float lsum0 = 0.0f, lsum1 = 0.0f;

    for (int t = 0; t < NT_; t++) {
        CP_WAIT1();
        __syncthreads();
        if (t + 2 < NT_) {
            const uint32_t kvb = smb + SMKV + (uint32_t)(((t + 2) % 3) * 16384);
            const __half* Kg = Kg0 + (size_t)(t + 2) * 64 * 64;
            const __half* Vg = Vg0 + (size_t)(t + 2) * 64 * 64;
            #pragma unroll
            for (int i = 0; i < 4; i++) {
                int idx = tid + 128 * i;
                int r = idx >> 3, ch = idx & 7;
                uint32_t d = swa8(r, ch);
                cpasync16(kvb + d,        Kg + (size_t)r * 64 + ch * 8);
                cpasync16(kvb + 8192 + d, Vg + (size_t)r * 64 + ch * 8);
            }
        }
        CP_COMMIT();

        const uint32_t smk = smb + SMKV + (uint32_t)((t % 3) * 16384);
        const uint32_t smv = smk + 8192;

        // ---- S = Q.K^T (single fp16 pass) ----
        float s[8][4];
        #pragma unroll
        for (int i = 0; i < 8; i++)
            #pragma unroll
            for (int j = 0; j < 4; j++) s[i][j] = 0.0f;

        #pragma unroll
        for (int ks = 0; ks < 4; ks++) {
            #pragma unroll
            for (int np = 0; np < 4; np++) {
                uint32_t kk[4];
                ldsm4(kk, smk + swa8(np * 16 + krow, ks * 2 + kchnk));
                mma16816h(s[2 * np],     qf[ks], kk[0], kk[1]);
                mma16816h(s[2 * np + 1], qf[ks], kk[2], kk[3]);
            }
        }

        // ---- exp2, sum, fp16 pack, PV (single pass) ----
        #pragma unroll
        for (int c = 0; c < 4; c++) {
            uint32_t a[4];
            #pragma unroll
            for (int h = 0; h < 2; h++) {
                float* sp = s[2 * c + h];
                float p0 = ex2f(sp[0]), p1 = ex2f(sp[1]);
                float p2 = ex2f(sp[2]), p3 = ex2f(sp[3]);
                lsum0 += p0 + p1;
                lsum1 += p2 + p3;
                a[2 * h]     = packh(p0, p1);
                a[2 * h + 1] = packh(p2, p3);
            }
            const int vrow = c * 16 + (l & 15);
            #pragma unroll
            for (int j = 0; j < 4; j++) {
                uint32_t vv[4];
                ldsm4t(vv, smv + swa8(vrow, 2 * j + vchnk));
                mma16816h(o[2 * j],     a, vv[0], vv[1]);
                mma16816h(o[2 * j + 1], a, vv[2], vv[3]);
            }
        }
    }

    // ---- epilogue ----
    lsum0 += __shfl_xor_sync(0xffffffffu, lsum0, 1);
    lsum0 += __shfl_xor_sync(0xffffffffu, lsum0, 2);
    lsum1 += __shfl_xor_sync(0xffffffffu, lsum1, 1);
    lsum1 += __shfl_xor_sync(0xffffffffu, lsum1, 2);
    const float inv0 = 1.0f / lsum0;
    const float inv1 = 1.0f / lsum1;

    const int row0 = q0 + w * 16 + (l >> 2);
    const int row1 = row0 + 8;
    const int colb = head * HD_ + 2 * (l & 3);
    float* out0 = out + ((size_t)b * S_ + row0) * H_ + colb;
    float* out1 = out + ((size_t)b * S_ + row1) * H_ + colb;
    #pragma unroll
    for (int nt = 0; nt < 8; nt++) {
        *(float2*)(out0 + nt * 8) = make_float2(o[nt][0] * inv0, o[nt][1] * inv0);
        *(float2*)(out1 + nt * 8) = make_float2(o[nt][2] * inv1, o[nt][3] * inv1);
    }
}

// ---------------------------------------------------------------------------
extern "C" void kernel_launch(void* const* d_in, const int* in_sizes, int n_in,
                              void* d_out, int out_size)
{
    (void)in_sizes; (void)n_in; (void)out_size;
    const float* X  = (const float*)d_in[0];
    const float* Wq = (const float*)d_in[1];
    const float* bq = (const float*)d_in[2];
    const float* Wk = (const float*)d_in[3];
    const float* bk = (const float*)d_in[4];
    const float* Wv = (const float*)d_in[5];
    const float* bv = (const float*)d_in[6];
    float* out = (float*)d_out;

    cudaFuncSetAttribute(qkv_mma_kernel,
                         cudaFuncAttributeMaxDynamicSharedMemorySize, GSM_TOT);
    cudaFuncSetAttribute(attn_kernel,
                         cudaFuncAttributeMaxDynamicSharedMemorySize, SMTOT);

    conv_x_kernel<<<(B_ * S_ * 384) / 256, 256>>>(X);
    conv_w_kernel<<<dim3(KB_, H_ / 64, 3), 256>>>(Wq, Wk, Wv);
    qkv_mma_kernel<<<dim3(H_ / 256, (B_ * S_) / 128, 3), 512, GSM_TOT>>>(bq, bk, bv);
    attn_kernel<<<dim3(S_ / 64, NH_, B_), 128, SMTOT>>>(out);
}

// round 10
// speedup vs baseline: 2.4911x; 1.4601x over previous
#include <cuda_runtime.h>
#include <cuda_fp16.h>
#include <cstdint>

#define B_  2
#define S_  2048
#define H_  768
#define NH_ 12
#define HD_ 64
#define KB_ 12          // 768 / 64 k-chunks

// fp16 projections: [bh][s][64]. Q pre-scaled by log2(e)/8.
__device__ __align__(16) __half g_qh[(size_t)B_ * NH_ * S_ * 64];
__device__ __align__(16) __half g_kh[(size_t)B_ * NH_ * S_ * 64];
__device__ __align__(16) __half g_vh[(size_t)B_ * NH_ * S_ * 64];
// fp16 GEMM inputs:
// g_xh: [4096][12][64]        g_wh: [3][768 n][12][64] (W transposed)
__device__ __align__(16) __half g_xh[(size_t)B_ * S_ * KB_ * 64];
__device__ __align__(16) __half g_wh[(size_t)3 * H_ * KB_ * 64];

// ============================ PTX helpers ==================================
__device__ __forceinline__ uint32_t smem_u32(const void* p) {
    uint32_t a;
    asm("{ .reg .u64 t; cvta.to.shared.u64 t, %1; cvt.u32.u64 %0, t; }"
        : "=r"(a) : "l"(p));
    return a;
}
__device__ __forceinline__ void cpasync16(uint32_t dst, const void* src) {
    asm volatile("cp.async.cg.shared.global [%0], [%1], 16;"
                 :: "r"(dst), "l"(src) : "memory");
}
#define CP_COMMIT() asm volatile("cp.async.commit_group;" ::: "memory")
#define CP_WAIT0()  asm volatile("cp.async.wait_group 0;" ::: "memory")
#define CP_WAIT1()  asm volatile("cp.async.wait_group 1;" ::: "memory")
#define CP_WAIT2()  asm volatile("cp.async.wait_group 2;" ::: "memory")

__device__ __forceinline__ void ldsm4(uint32_t r[4], uint32_t addr) {
    asm volatile("ldmatrix.sync.aligned.m8n8.x4.shared.b16 {%0,%1,%2,%3}, [%4];"
        : "=r"(r[0]), "=r"(r[1]), "=r"(r[2]), "=r"(r[3]) : "r"(addr));
}
__device__ __forceinline__ void ldsm4t(uint32_t r[4], uint32_t addr) {
    asm volatile("ldmatrix.sync.aligned.m8n8.x4.trans.shared.b16 {%0,%1,%2,%3}, [%4];"
        : "=r"(r[0]), "=r"(r[1]), "=r"(r[2]), "=r"(r[3]) : "r"(addr));
}
// fp16 MMA
__device__ __forceinline__ void mma16816h(float c[4], const uint32_t a[4],
                                          uint32_t b0, uint32_t b1) {
    asm volatile("mma.sync.aligned.m16n8k16.row.col.f32.f16.f16.f32 "
        "{%0,%1,%2,%3}, {%4,%5,%6,%7}, {%8,%9}, {%0,%1,%2,%3};"
        : "+f"(c[0]), "+f"(c[1]), "+f"(c[2]), "+f"(c[3])
        : "r"(a[0]), "r"(a[1]), "r"(a[2]), "r"(a[3]), "r"(b0), "r"(b1));
}
__device__ __forceinline__ float ex2f(float x) {
    float y; asm("ex2.approx.f32 %0, %1;" : "=f"(y) : "f"(x)); return y;
}
// pack two fp32 -> f16x2 (first arg -> bits [15:0])
__device__ __forceinline__ uint32_t packh(float lo, float hi) {
    uint32_t r; asm("cvt.rn.f16x2.f32 %0, %1, %2;" : "=r"(r) : "f"(hi), "f"(lo));
    return r;
}
// 128B rows (64 fp16), 8 chunks of 16B, XOR swizzle -> conflict-free ldmatrix
__device__ __forceinline__ uint32_t swa8(int row, int chunk) {
    return (uint32_t)(row * 128 + ((chunk ^ (row & 7)) << 4));
}

// ---------------------------------------------------------------------------
// conv_x: X fp32 [4096][768] -> g_xh fp16 [m][kb][64].
// ---------------------------------------------------------------------------
__global__ __launch_bounds__(256) void conv_x_kernel(const float* __restrict__ X)
{
    const int t = blockIdx.x * 256 + threadIdx.x;     // 4096*384 threads
    const int m = t / 384, r = t % 384;
    const int kb = r >> 5, pr = r & 31;
    float2 x = *(const float2*)(X + (size_t)m * H_ + kb * 64 + 2 * pr);
    uint32_t* dst = (uint32_t*)(g_xh + ((size_t)m * KB_ + kb) * 64);
    dst[pr] = packh(x.x, x.y);
}

// ---------------------------------------------------------------------------
// conv_w: W fp32 [768 k][768 n] -> g_wh fp16 [which][n][kb][64] (transposed).
// ---------------------------------------------------------------------------
__global__ __launch_bounds__(256) void conv_w_kernel(
    const float* __restrict__ Wq, const float* __restrict__ Wk,
    const float* __restrict__ Wv)
{
    const int kb = blockIdx.x, ng = blockIdx.y, which = blockIdx.z;
    const float* W = (which == 0) ? Wq : (which == 1) ? Wk : Wv;

    __shared__ float T[64][65];
    const int tid = threadIdx.x;
    #pragma unroll
    for (int i = 0; i < 16; i++) {
        int idx = tid + 256 * i;
        int r = idx >> 6, c = idx & 63;      // r = k-local, c = n-local
        T[r][c] = W[(size_t)(kb * 64 + r) * H_ + ng * 64 + c];
    }
    __syncthreads();

    const int n  = tid >> 2;
    const int jb = tid & 3;
    uint32_t* dst = (uint32_t*)(g_wh +
        (((size_t)which * H_ + ng * 64 + n) * KB_ + kb) * 64);
    #pragma unroll
    for (int j = 0; j < 8; j++) {
        int k2 = jb * 8 + j;
        dst[k2] = packh(T[2 * k2][n], T[2 * k2 + 1][n]);
    }
}

// ---------------------------------------------------------------------------
// fp16 HMMA QKV GEMM (single pass): 512 thr (16 warps, 4m x 4n),
// tile 128m x 256n (4 heads), 64-k chunks triple-buffered (prefetch dist 2).
// smem 3 x (A 16KB + B 32KB) = 144KB, 1 CTA/SM. Epilogue emits fp16.
// ---------------------------------------------------------------------------
#define GSM_TOT 147456
#define GBUF    49152

__global__ void __launch_bounds__(512, 1) qkv_mma_kernel(
    const float* __restrict__ bq, const float* __restrict__ bk,
    const float* __restrict__ bv)
{
    extern __shared__ char sm[];
    const uint32_t smb = smem_u32(sm);

    const int tid = threadIdx.x;
    const int l = tid & 31, w = tid >> 5;
    const int wm = w & 3, wn = w >> 2;           // 4 m-warps x 4 n-warps
    const int which = blockIdx.z;
    const int m0 = blockIdx.y * 128;
    const int n0 = blockIdx.x * 256;

    const __half* Ag = g_xh + (size_t)m0 * KB_ * 64;
    const __half* Bg = g_wh + ((size_t)which * H_ + n0) * KB_ * 64;

    float s[2][8][4];
    #pragma unroll
    for (int mt = 0; mt < 2; mt++)
        #pragma unroll
        for (int nt = 0; nt < 8; nt++)
            #pragma unroll
            for (int j = 0; j < 4; j++) s[mt][nt][j] = 0.0f;

    const int arow0 = 32 * wm + (l & 15);
    const int achnk = l >> 4;
    const int krow  = 64 * wn + (l & 7) + ((l >> 4) << 3);
    const int kchnk = (l >> 3) & 1;

    // prologue: chunks 0 and 1 into buffers 0 and 1
    #pragma unroll
    for (int pb = 0; pb < 2; pb++) {
        const uint32_t off = (uint32_t)(pb * GBUF);
        #pragma unroll
        for (int i = 0; i < 2; i++) {        // A: 128 rows x 8 chunks = 1024
            int idx = tid + 512 * i;
            int r = idx >> 3, ch = idx & 7;
            cpasync16(smb + off + swa8(r, ch),
                      Ag + ((size_t)r * KB_ + pb) * 64 + ch * 8);
        }
        #pragma unroll
        for (int i = 0; i < 4; i++) {        // B: 256 rows x 8 chunks = 2048
            int idx = tid + 512 * i;
            int r = idx >> 3, ch = idx & 7;
            cpasync16(smb + off + 16384 + swa8(r, ch),
                      Bg + ((size_t)r * KB_ + pb) * 64 + ch * 8);
        }
        CP_COMMIT();
    }

    for (int kb = 0; kb < KB_; kb++) {
        CP_WAIT1();          // chunk kb resident
        __syncthreads();     // all warps past compute(kb-1); buffer (kb+2)%3 free
        if (kb + 2 < KB_) {
            const uint32_t off = (uint32_t)(((kb + 2) % 3) * GBUF);
            #pragma unroll
            for (int i = 0; i < 2; i++) {
                int idx = tid + 512 * i;
                int r = idx >> 3, ch = idx & 7;
                cpasync16(smb + off + swa8(r, ch),
                          Ag + ((size_t)r * KB_ + kb + 2) * 64 + ch * 8);
            }
            #pragma unroll
            for (int i = 0; i < 4; i++) {
                int idx = tid + 512 * i;
                int r = idx >> 3, ch = idx & 7;
                cpasync16(smb + off + 16384 + swa8(r, ch),
                          Bg + ((size_t)r * KB_ + kb + 2) * 64 + ch * 8);
            }
        }
        CP_COMMIT();         // always commit (uniform group counting)

        const uint32_t smA = smb + (uint32_t)((kb % 3) * GBUF);
        const uint32_t smB = smA + 16384;

        #pragma unroll
        for (int ks = 0; ks < 4; ks++) {
            uint32_t a[2][4], bb[4][4];
            #pragma unroll
            for (int mt = 0; mt < 2; mt++)
                ldsm4(a[mt], smA + swa8(arow0 + 16 * mt, ks * 2 + achnk));
            #pragma unroll
            for (int bt = 0; bt < 4; bt++)
                ldsm4(bb[bt], smB + swa8(16 * bt + krow, ks * 2 + kchnk));
            #pragma unroll
            for (int mt = 0; mt < 2; mt++)
                #pragma unroll
                for (int bt = 0; bt < 4; bt++) {
                    mma16816h(s[mt][2 * bt],     a[mt], bb[bt][0], bb[bt][1]);
                    mma16816h(s[mt][2 * bt + 1], a[mt], bb[bt][2], bb[bt][3]);
                }
        }
    }

    // ---- epilogue: +bias, (Q: *log2e/8), fp16 pack, store [bh][s][64] ----
    const float* bias = (which == 0) ? bq : (which == 1) ? bk : bv;
    __half* Gp = (which == 0) ? g_qh : (which == 1) ? g_kh : g_vh;
    const float sc = (which == 0) ? 0.18033688011112042f : 1.0f;  // log2(e)/8

    const int head = 4 * blockIdx.x + wn;
    #pragma unroll
    for (int mt = 0; mt < 2; mt++) {
        const int r0 = m0 + 32 * wm + 16 * mt + (l >> 2);
        const int b  = r0 >> 11;
        const int s0 = r0 & (S_ - 1);
        const int bh_ = b * NH_ + head;
        uint32_t* d0 = (uint32_t*)(Gp + ((size_t)bh_ * S_ + s0) * 64);
        uint32_t* d1 = (uint32_t*)(Gp + ((size_t)bh_ * S_ + s0 + 8) * 64);
        #pragma unroll
        for (int nt = 0; nt < 8; nt++) {
            const int c0 = 8 * nt + 2 * (l & 3);
            const float b0 = __ldg(bias + head * 64 + c0);
            const float b1 = __ldg(bias + head * 64 + c0 + 1);
            d0[c0 >> 1] = packh((s[mt][nt][0] + b0) * sc, (s[mt][nt][1] + b1) * sc);
            d1[c0 >> 1] = packh((s[mt][nt][2] + b0) * sc, (s[mt][nt][3] + b1) * sc);
        }
    }
}

// ---------------------------------------------------------------------------
// fp16 HMMA flash attention (Round-9 best): single-pass QK and PV, no-max
// softmax in log2 domain. q-tile 64, kv-tile 64, triple-buffered prefetch,
// Q frags in registers. smem: Q 8KB + 3 x 16KB = 56KB; 3 CTAs/SM.
// ---------------------------------------------------------------------------
#define SMQ   0
#define SMKV  8192
#define SMTOT 57344
#define NT_   (S_ / 64)

__global__ void __launch_bounds__(128, 3) attn_kernel(float* __restrict__ out)
{
    extern __shared__ char sm[];
    const uint32_t smb = smem_u32(sm);
    const uint32_t smq = smb + SMQ;

    const int tid = threadIdx.x;
    const int l = tid & 31, w = tid >> 5;
    const int head = blockIdx.y, b = blockIdx.z;
    const int bh = b * NH_ + head;
    const int q0 = blockIdx.x * 64;

    const __half* Kg0 = g_kh + (size_t)bh * S_ * 64;
    const __half* Vg0 = g_vh + (size_t)bh * S_ * 64;

    // --- prologue: Q, kv0, kv1 (three cp.async groups) ---
    {
        const __half* Qg = g_qh + ((size_t)bh * S_ + q0) * 64;
        #pragma unroll
        for (int i = 0; i < 4; i++) {
            int idx = tid + 128 * i;
            int r = idx >> 3, ch = idx & 7;
            cpasync16(smq + swa8(r, ch), Qg + (size_t)r * 64 + ch * 8);
        }
        CP_COMMIT();
    }
    #pragma unroll
    for (int pb = 0; pb < 2; pb++) {
        const uint32_t kvb = smb + SMKV + (uint32_t)(pb * 16384);
        const __half* Kg = Kg0 + (size_t)pb * 64 * 64;
        const __half* Vg = Vg0 + (size_t)pb * 64 * 64;
        #pragma unroll
        for (int i = 0; i < 4; i++) {
            int idx = tid + 128 * i;
            int r = idx >> 3, ch = idx & 7;
            uint32_t d = swa8(r, ch);
            cpasync16(kvb + d,        Kg + (size_t)r * 64 + ch * 8);
            cpasync16(kvb + 8192 + d, Vg + (size_t)r * 64 + ch * 8);
        }
        CP_COMMIT();
    }

    // fragment lane constants
    const int arow  = (w << 4) + (l & 15);
    const int achnk = l >> 4;
    const int krow  = (l & 7) + ((l >> 4) << 3);
    const int kchnk = (l >> 3) & 1;
    const int vchnk = l >> 4;

    // --- hoist Q fragments into registers ---
    CP_WAIT2();
    __syncthreads();
    uint32_t qf[4][4];
    #pragma unroll
    for (int ks = 0; ks < 4; ks++)
        ldsm4(qf[ks], smq + swa8(arow, ks * 2 + achnk));

    float o[8][4];
    #pragma unroll
    for (int i = 0; i < 8; i++)
        #pragma unroll
        for (int j = 0; j < 4; j++) o[i][j] = 0.0f;
    float lsum0 = 0.0f, lsum1 = 0.0f;

    for (int t = 0; t < NT_; t++) {
        CP_WAIT1();
        __syncthreads();
        if (t + 2 < NT_) {
            const uint32_t kvb = smb + SMKV + (uint32_t)(((t + 2) % 3) * 16384);
            const __half* Kg = Kg0 + (size_t)(t + 2) * 64 * 64;
            const __half* Vg = Vg0 + (size_t)(t + 2) * 64 * 64;
            #pragma unroll
            for (int i = 0; i < 4; i++) {
                int idx = tid + 128 * i;
                int r = idx >> 3, ch = idx & 7;
                uint32_t d = swa8(r, ch);
                cpasync16(kvb + d,        Kg + (size_t)r * 64 + ch * 8);
                cpasync16(kvb + 8192 + d, Vg + (size_t)r * 64 + ch * 8);
            }
        }
        CP_COMMIT();

        const uint32_t smk = smb + SMKV + (uint32_t)((t % 3) * 16384);
        const uint32_t smv = smk + 8192;

        // ---- S = Q.K^T (single fp16 pass) ----
        float s[8][4];
        #pragma unroll
        for (int i = 0; i < 8; i++)
            #pragma unroll
            for (int j = 0; j < 4; j++) s[i][j] = 0.0f;

        #pragma unroll
        for (int ks = 0; ks < 4; ks++) {
            #pragma unroll
            for (int np = 0; np < 4; np++) {
                uint32_t kk[4];
                ldsm4(kk, smk + swa8(np * 16 + krow, ks * 2 + kchnk));
                mma16816h(s[2 * np],     qf[ks], kk[0], kk[1]);
                mma16816h(s[2 * np + 1], qf[ks], kk[2], kk[3]);
            }
        }

        // ---- exp2, sum, fp16 pack, PV (single pass) ----
        #pragma unroll
        for (int c = 0; c < 4; c++) {
            uint32_t a[4];
            #pragma unroll
            for (int h = 0; h < 2; h++) {
                float* sp = s[2 * c + h];
                float p0 = ex2f(sp[0]), p1 = ex2f(sp[1]);
                float p2 = ex2f(sp[2]), p3 = ex2f(sp[3]);
                lsum0 += p0 + p1;
                lsum1 += p2 + p3;
                a[2 * h]     = packh(p0, p1);
                a[2 * h + 1] = packh(p2, p3);
            }
            const int vrow = c * 16 + (l & 15);
            #pragma unroll
            for (int j = 0; j < 4; j++) {
                uint32_t vv[4];
                ldsm4t(vv, smv + swa8(vrow, 2 * j + vchnk));
                mma16816h(o[2 * j],     a, vv[0], vv[1]);
                mma16816h(o[2 * j + 1], a, vv[2], vv[3]);
            }
        }
    }

    // ---- epilogue ----
    lsum0 += __shfl_xor_sync(0xffffffffu, lsum0, 1);
    lsum0 += __shfl_xor_sync(0xffffffffu, lsum0, 2);
    lsum1 += __shfl_xor_sync(0xffffffffu, lsum1, 1);
    lsum1 += __shfl_xor_sync(0xffffffffu, lsum1, 2);
    const float inv0 = 1.0f / lsum0;
    const float inv1 = 1.0f / lsum1;

    const int row0 = q0 + w * 16 + (l >> 2);
    const int row1 = row0 + 8;
    const int colb = head * HD_ + 2 * (l & 3);
    float* out0 = out + ((size_t)b * S_ + row0) * H_ + colb;
    float* out1 = out + ((size_t)b * S_ + row1) * H_ + colb;
    #pragma unroll
    for (int nt = 0; nt < 8; nt++) {
        *(float2*)(out0 + nt * 8) = make_float2(o[nt][0] * inv0, o[nt][1] * inv0);
        *(float2*)(out1 + nt * 8) = make_float2(o[nt][2] * inv1, o[nt][3] * inv1);
    }
}

// ---------------------------------------------------------------------------
extern "C" void kernel_launch(void* const* d_in, const int* in_sizes, int n_in,
                              void* d_out, int out_size)
{
    (void)in_sizes; (void)n_in; (void)out_size;
    const float* X  = (const float*)d_in[0];
    const float* Wq = (const float*)d_in[1];
    const float* bq = (const float*)d_in[2];
    const float* Wk = (const float*)d_in[3];
    const float* bk = (const float*)d_in[4];
    const float* Wv = (const float*)d_in[5];
    const float* bv = (const float*)d_in[6];
    float* out = (float*)d_out;

    cudaFuncSetAttribute(qkv_mma_kernel,
                         cudaFuncAttributeMaxDynamicSharedMemorySize, GSM_TOT);
    cudaFuncSetAttribute(attn_kernel,
                         cudaFuncAttributeMaxDynamicSharedMemorySize, SMTOT);

    conv_x_kernel<<<(B_ * S_ * 384) / 256, 256>>>(X);
    conv_w_kernel<<<dim3(KB_, H_ / 64, 3), 256>>>(Wq, Wk, Wv);
    qkv_mma_kernel<<<dim3(H_ / 256, (B_ * S_) / 128, 3), 512, GSM_TOT>>>(bq, bk, bv);
    attn_kernel<<<dim3(S_ / 64, NH_, B_), 128, SMTOT>>>(out);
}

// round 11
// speedup vs baseline: 2.6201x; 1.0518x over previous
#include <cuda_runtime.h>
#include <cuda_fp16.h>
#include <cstdint>

#define B_  2
#define S_  2048
#define H_  768
#define NH_ 12
#define HD_ 64
#define KB_ 12          // 768 / 64 k-chunks

// fp16 projections: [bh][s][64]. Q pre-scaled by log2(e)/8.
__device__ __align__(16) __half g_qh[(size_t)B_ * NH_ * S_ * 64];
__device__ __align__(16) __half g_kh[(size_t)B_ * NH_ * S_ * 64];
__device__ __align__(16) __half g_vh[(size_t)B_ * NH_ * S_ * 64];
// fp16 GEMM inputs:
__device__ __align__(16) __half g_xh[(size_t)B_ * S_ * KB_ * 64];
__device__ __align__(16) __half g_wh[(size_t)3 * H_ * KB_ * 64];

// ============================ PTX helpers ==================================
__device__ __forceinline__ uint32_t smem_u32(const void* p) {
    uint32_t a;
    asm("{ .reg .u64 t; cvta.to.shared.u64 t, %1; cvt.u32.u64 %0, t; }"
        : "=r"(a) : "l"(p));
    return a;
}
__device__ __forceinline__ void cpasync16(uint32_t dst, const void* src) {
    asm volatile("cp.async.cg.shared.global [%0], [%1], 16;"
                 :: "r"(dst), "l"(src) : "memory");
}
#define CP_COMMIT() asm volatile("cp.async.commit_group;" ::: "memory")
#define CP_WAIT0()  asm volatile("cp.async.wait_group 0;" ::: "memory")
#define CP_WAIT1()  asm volatile("cp.async.wait_group 1;" ::: "memory")
#define CP_WAIT2()  asm volatile("cp.async.wait_group 2;" ::: "memory")

__device__ __forceinline__ void ldsm4(uint32_t r[4], uint32_t addr) {
    asm volatile("ldmatrix.sync.aligned.m8n8.x4.shared.b16 {%0,%1,%2,%3}, [%4];"
        : "=r"(r[0]), "=r"(r[1]), "=r"(r[2]), "=r"(r[3]) : "r"(addr));
}
__device__ __forceinline__ void ldsm4t(uint32_t r[4], uint32_t addr) {
    asm volatile("ldmatrix.sync.aligned.m8n8.x4.trans.shared.b16 {%0,%1,%2,%3}, [%4];"
        : "=r"(r[0]), "=r"(r[1]), "=r"(r[2]), "=r"(r[3]) : "r"(addr));
}
// fp16 MMA, fp32 accumulate
__device__ __forceinline__ void mma16816h(float c[4], const uint32_t a[4],
                                          uint32_t b0, uint32_t b1) {
    asm volatile("mma.sync.aligned.m16n8k16.row.col.f32.f16.f16.f32 "
        "{%0,%1,%2,%3}, {%4,%5,%6,%7}, {%8,%9}, {%0,%1,%2,%3};"
        : "+f"(c[0]), "+f"(c[1]), "+f"(c[2]), "+f"(c[3])
        : "r"(a[0]), "r"(a[1]), "r"(a[2]), "r"(a[3]), "r"(b0), "r"(b1));
}
// pack two fp32 -> f16x2 (first arg -> bits [15:0])
__device__ __forceinline__ uint32_t packh(float lo, float hi) {
    uint32_t r; asm("cvt.rn.f16x2.f32 %0, %1, %2;" : "=r"(r) : "f"(hi), "f"(lo));
    return r;
}
// packed fp16x2 exp2
__device__ __forceinline__ uint32_t ex2h2(uint32_t x) {
    uint32_t y; asm("ex2.approx.f16x2 %0, %1;" : "=r"(y) : "r"(x)); return y;
}
// 128B rows (64 fp16), 8 chunks of 16B, XOR swizzle -> conflict-free ldmatrix
__device__ __forceinline__ uint32_t swa8(int row, int chunk) {
    return (uint32_t)(row * 128 + ((chunk ^ (row & 7)) << 4));
}

// ---------------------------------------------------------------------------
// conv_x: X fp32 [4096][768] -> g_xh fp16 [m][kb][64].
// ---------------------------------------------------------------------------
__global__ __launch_bounds__(256) void conv_x_kernel(const float* __restrict__ X)
{
    const int t = blockIdx.x * 256 + threadIdx.x;
    const int m = t / 384, r = t % 384;
    const int kb = r >> 5, pr = r & 31;
    float2 x = *(const float2*)(X + (size_t)m * H_ + kb * 64 + 2 * pr);
    uint32_t* dst = (uint32_t*)(g_xh + ((size_t)m * KB_ + kb) * 64);
    dst[pr] = packh(x.x, x.y);
}

// ---------------------------------------------------------------------------
// conv_w: W fp32 [768 k][768 n] -> g_wh fp16 [which][n][kb][64] (transposed).
// ---------------------------------------------------------------------------
__global__ __launch_bounds__(256) void conv_w_kernel(
    const float* __restrict__ Wq, const float* __restrict__ Wk,
    const float* __restrict__ Wv)
{
    const int kb = blockIdx.x, ng = blockIdx.y, which = blockIdx.z;
    const float* W = (which == 0) ? Wq : (which == 1) ? Wk : Wv;

    __shared__ float T[64][65];
    const int tid = threadIdx.x;
    #pragma unroll
    for (int i = 0; i < 16; i++) {
        int idx = tid + 256 * i;
        int r = idx >> 6, c = idx & 63;
        T[r][c] = W[(size_t)(kb * 64 + r) * H_ + ng * 64 + c];
    }
    __syncthreads();

    const int n  = tid >> 2;
    const int jb = tid & 3;
    uint32_t* dst = (uint32_t*)(g_wh +
        (((size_t)which * H_ + ng * 64 + n) * KB_ + kb) * 64);
    #pragma unroll
    for (int j = 0; j < 8; j++) {
        int k2 = jb * 8 + j;
        dst[k2] = packh(T[2 * k2][n], T[2 * k2 + 1][n]);
    }
}

// ---------------------------------------------------------------------------
// fp16 HMMA QKV GEMM (single pass): 512 thr (16 warps, 4m x 4n),
// tile 128m x 256n (4 heads), 64-k chunks triple-buffered.
// smem 3 x (A 16KB + B 32KB) = 144KB, 1 CTA/SM. Epilogue emits fp16.
// ---------------------------------------------------------------------------
#define GSM_TOT 147456
#define GBUF    49152

__global__ void __launch_bounds__(512, 1) qkv_mma_kernel(
    const float* __restrict__ bq, const float* __restrict__ bk,
    const float* __restrict__ bv)
{
    extern __shared__ char sm[];
    const uint32_t smb = smem_u32(sm);

    const int tid = threadIdx.x;
    const int l = tid & 31, w = tid >> 5;
    const int wm = w & 3, wn = w >> 2;
    const int which = blockIdx.z;
    const int m0 = blockIdx.y * 128;
    const int n0 = blockIdx.x * 256;

    const __half* Ag = g_xh + (size_t)m0 * KB_ * 64;
    const __half* Bg = g_wh + ((size_t)which * H_ + n0) * KB_ * 64;

    float s[2][8][4];
    #pragma unroll
    for (int mt = 0; mt < 2; mt++)
        #pragma unroll
        for (int nt = 0; nt < 8; nt++)
            #pragma unroll
            for (int j = 0; j < 4; j++) s[mt][nt][j] = 0.0f;

    const int arow0 = 32 * wm + (l & 15);
    const int achnk = l >> 4;
    const int krow  = 64 * wn + (l & 7) + ((l >> 4) << 3);
    const int kchnk = (l >> 3) & 1;

    #pragma unroll
    for (int pb = 0; pb < 2; pb++) {
        const uint32_t off = (uint32_t)(pb * GBUF);
        #pragma unroll
        for (int i = 0; i < 2; i++) {
            int idx = tid + 512 * i;
            int r = idx >> 3, ch = idx & 7;
            cpasync16(smb + off + swa8(r, ch),
                      Ag + ((size_t)r * KB_ + pb) * 64 + ch * 8);
        }
        #pragma unroll
        for (int i = 0; i < 4; i++) {
            int idx = tid + 512 * i;
            int r = idx >> 3, ch = idx & 7;
            cpasync16(smb + off + 16384 + swa8(r, ch),
                      Bg + ((size_t)r * KB_ + pb) * 64 + ch * 8);
        }
        CP_COMMIT();
    }

    for (int kb = 0; kb < KB_; kb++) {
        CP_WAIT1();
        __syncthreads();
        if (kb + 2 < KB_) {
            const uint32_t off = (uint32_t)(((kb + 2) % 3) * GBUF);
            #pragma unroll
            for (int i = 0; i < 2; i++) {
                int idx = tid + 512 * i;
                int r = idx >> 3, ch = idx & 7;
                cpasync16(smb + off + swa8(r, ch),
                          Ag + ((size_t)r * KB_ + kb + 2) * 64 + ch * 8);
            }
            #pragma unroll
            for (int i = 0; i < 4; i++) {
                int idx = tid + 512 * i;
                int r = idx >> 3, ch = idx & 7;
                cpasync16(smb + off + 16384 + swa8(r, ch),
                          Bg + ((size_t)r * KB_ + kb + 2) * 64 + ch * 8);
            }
        }
        CP_COMMIT();

        const uint32_t smA = smb + (uint32_t)((kb % 3) * GBUF);
        const uint32_t smB = smA + 16384;

        #pragma unroll
        for (int ks = 0; ks < 4; ks++) {
            uint32_t a[2][4], bb[4][4];
            #pragma unroll
            for (int mt = 0; mt < 2; mt++)
                ldsm4(a[mt], smA + swa8(arow0 + 16 * mt, ks * 2 + achnk));
            #pragma unroll
            for (int bt = 0; bt < 4; bt++)
                ldsm4(bb[bt], smB + swa8(16 * bt + krow, ks * 2 + kchnk));
            #pragma unroll
            for (int mt = 0; mt < 2; mt++)
                #pragma unroll
                for (int bt = 0; bt < 4; bt++) {
                    mma16816h(s[mt][2 * bt],     a[mt], bb[bt][0], bb[bt][1]);
                    mma16816h(s[mt][2 * bt + 1], a[mt], bb[bt][2], bb[bt][3]);
                }
        }
    }

    // ---- epilogue: +bias, (Q: *log2e/8), fp16 pack, store [bh][s][64] ----
    const float* bias = (which == 0) ? bq : (which == 1) ? bk : bv;
    __half* Gp = (which == 0) ? g_qh : (which == 1) ? g_kh : g_vh;
    const float sc = (which == 0) ? 0.18033688011112042f : 1.0f;

    const int head = 4 * blockIdx.x + wn;
    #pragma unroll
    for (int mt = 0; mt < 2; mt++) {
        const int r0 = m0 + 32 * wm + 16 * mt + (l >> 2);
        const int b  = r0 >> 11;
        const int s0 = r0 & (S_ - 1);
        const int bh_ = b * NH_ + head;
        uint32_t* d0 = (uint32_t*)(Gp + ((size_t)bh_ * S_ + s0) * 64);
        uint32_t* d1 = (uint32_t*)(Gp + ((size_t)bh_ * S_ + s0 + 8) * 64);
        #pragma unroll
        for (int nt = 0; nt < 8; nt++) {
            const int c0 = 8 * nt + 2 * (l & 3);
            const float b0 = __ldg(bias + head * 64 + c0);
            const float b1 = __ldg(bias + head * 64 + c0 + 1);
            d0[c0 >> 1] = packh((s[mt][nt][0] + b0) * sc, (s[mt][nt][1] + b1) * sc);
            d1[c0 >> 1] = packh((s[mt][nt][2] + b0) * sc, (s[mt][nt][3] + b1) * sc);
        }
    }
}

// ---------------------------------------------------------------------------
// fp16 HMMA flash attention v3: q-tile 128/CTA (2 sets of 64), kv-tile 64,
// K/V fragments shared across sets, f16x2 exp, row-sums via ones-MMA.
// smem: Q 16KB + 3 x 16KB = 64KB; 2 CTAs/SM (8 warps).
// ---------------------------------------------------------------------------
#define SMQ   0
#define SMKV  16384
#define SMTOT 65536
#define NT_   (S_ / 64)

__global__ void __launch_bounds__(128, 2) attn_kernel(float* __restrict__ out)
{
    extern __shared__ char sm[];
    const uint32_t smb = smem_u32(sm);
    const uint32_t smq = smb + SMQ;

    const int tid = threadIdx.x;
    const int l = tid & 31, w = tid >> 5;
    const int head = blockIdx.y, b = blockIdx.z;
    const int bh = b * NH_ + head;
    const int q0 = blockIdx.x * 128;

    const __half* Kg0 = g_kh + (size_t)bh * S_ * 64;
    const __half* Vg0 = g_vh + (size_t)bh * S_ * 64;

    // --- prologue: Q (128 rows), kv0, kv1 ---
    {
        const __half* Qg = g_qh + ((size_t)bh * S_ + q0) * 64;
        #pragma unroll
        for (int i = 0; i < 8; i++) {
            int idx = tid + 128 * i;
            int r = idx >> 3, ch = idx & 7;
            cpasync16(smq + swa8(r, ch), Qg + (size_t)r * 64 + ch * 8);
        }
        CP_COMMIT();
    }
    #pragma unroll
    for (int pb = 0; pb < 2; pb++) {
        const uint32_t kvb = smb + SMKV + (uint32_t)(pb * 16384);
        const __half* Kg = Kg0 + (size_t)pb * 64 * 64;
        const __half* Vg = Vg0 + (size_t)pb * 64 * 64;
        #pragma unroll
        for (int i = 0; i < 4; i++) {
            int idx = tid + 128 * i;
            int r = idx >> 3, ch = idx & 7;
            uint32_t d = swa8(r, ch);
            cpasync16(kvb + d,        Kg + (size_t)r * 64 + ch * 8);
            cpasync16(kvb + 8192 + d, Vg + (size_t)r * 64 + ch * 8);
        }
        CP_COMMIT();
    }

    // fragment lane constants
    const int arow  = (w << 4) + (l & 15);
    const int achnk = l >> 4;
    const int krow  = (l & 7) + ((l >> 4) << 3);
    const int kchnk = (l >> 3) & 1;
    const int vchnk = l >> 4;
    const uint32_t ONES = 0x3C003C00u;   // fp16 (1.0, 1.0)

    // --- hoist Q fragments (both sets) into registers ---
    CP_WAIT2();
    __syncthreads();
    uint32_t qf[2][4][4];
    #pragma unroll
    for (int st = 0; st < 2; st++)
        #pragma unroll
        for (int ks = 0; ks < 4; ks++)
            ldsm4(qf[st][ks], smq + swa8(st * 64 + arow, ks * 2 + achnk));

    float o[2][8][4];
    #pragma unroll
    for (int st = 0; st < 2; st++)
        #pragma unroll
        for (int i = 0; i < 8; i++)
            #pragma unroll
            for (int j = 0; j < 4; j++) o[st][i][j] = 0.0f;
    float lacc[2][4];
    #pragma unroll
    for (int st = 0; st < 2; st++)
        #pragma unroll
        for (int j = 0; j < 4; j++) lacc[st][j] = 0.0f;

    for (int t = 0; t < NT_; t++) {
        CP_WAIT1();
        __syncthreads();
        if (t + 2 < NT_) {
            const uint32_t kvb = smb + SMKV + (uint32_t)(((t + 2) % 3) * 16384);
            const __half* Kg = Kg0 + (size_t)(t + 2) * 64 * 64;
            const __half* Vg = Vg0 + (size_t)(t + 2) * 64 * 64;
            #pragma unroll
            for (int i = 0; i < 4; i++) {
                int idx = tid + 128 * i;
                int r = idx >> 3, ch = idx & 7;
                uint32_t d = swa8(r, ch);
                cpasync16(kvb + d,        Kg + (size_t)r * 64 + ch * 8);
                cpasync16(kvb + 8192 + d, Vg + (size_t)r * 64 + ch * 8);
            }
        }
        CP_COMMIT();

        const uint32_t smk = smb + SMKV + (uint32_t)((t % 3) * 16384);
        const uint32_t smv = smk + 8192;

        // ---- S = Q.K^T for both q-sets, K fragments loaded once ----
        float s0[8][4], s1[8][4];
        #pragma unroll
        for (int i = 0; i < 8; i++)
            #pragma unroll
            for (int j = 0; j < 4; j++) { s0[i][j] = 0.0f; s1[i][j] = 0.0f; }

        #pragma unroll
        for (int ks = 0; ks < 4; ks++) {
            #pragma unroll
            for (int np = 0; np < 4; np++) {
                uint32_t kk[4];
                ldsm4(kk, smk + swa8(np * 16 + krow, ks * 2 + kchnk));
                mma16816h(s0[2 * np],     qf[0][ks], kk[0], kk[1]);
                mma16816h(s0[2 * np + 1], qf[0][ks], kk[2], kk[3]);
                mma16816h(s1[2 * np],     qf[1][ks], kk[0], kk[1]);
                mma16816h(s1[2 * np + 1], qf[1][ks], kk[2], kk[3]);
            }
        }

        // ---- exp2 (f16x2), row-sums via ones-MMA, PV with shared V frags ----
        #pragma unroll
        for (int c = 0; c < 4; c++) {
            uint32_t a0[4], a1[4];
            #pragma unroll
            for (int h = 0; h < 2; h++) {
                float* p0 = s0[2 * c + h];
                float* p1 = s1[2 * c + h];
                a0[2 * h]     = ex2h2(packh(p0[0], p0[1]));
                a0[2 * h + 1] = ex2h2(packh(p0[2], p0[3]));
                a1[2 * h]     = ex2h2(packh(p1[0], p1[1]));
                a1[2 * h + 1] = ex2h2(packh(p1[2], p1[3]));
            }
            mma16816h(lacc[0], a0, ONES, ONES);
            mma16816h(lacc[1], a1, ONES, ONES);

            const int vrow = c * 16 + (l & 15);
            #pragma unroll
            for (int j = 0; j < 4; j++) {
                uint32_t vv[4];
                ldsm4t(vv, smv + swa8(vrow, 2 * j + vchnk));
                mma16816h(o[0][2 * j],     a0, vv[0], vv[1]);
                mma16816h(o[0][2 * j + 1], a0, vv[2], vv[3]);
                mma16816h(o[1][2 * j],     a1, vv[0], vv[1]);
                mma16816h(o[1][2 * j + 1], a1, vv[2], vv[3]);
            }
        }
    }

    // ---- epilogue: ones-MMA already produced complete row sums ----
    const int colb = head * HD_ + 2 * (l & 3);
    #pragma unroll
    for (int st = 0; st < 2; st++) {
        const float inv0 = 1.0f / lacc[st][0];
        const float inv1 = 1.0f / lacc[st][2];
        const int row0 = q0 + st * 64 + w * 16 + (l >> 2);
        const int row1 = row0 + 8;
        float* out0 = out + ((size_t)b * S_ + row0) * H_ + colb;
        float* out1 = out + ((size_t)b * S_ + row1) * H_ + colb;
        #pragma unroll
        for (int nt = 0; nt < 8; nt++) {
            *(float2*)(out0 + nt * 8) =
                make_float2(o[st][nt][0] * inv0, o[st][nt][1] * inv0);
            *(float2*)(out1 + nt * 8) =
                make_float2(o[st][nt][2] * inv1, o[st][nt][3] * inv1);
        }
    }
}

// ---------------------------------------------------------------------------
extern "C" void kernel_launch(void* const* d_in, const int* in_sizes, int n_in,
                              void* d_out, int out_size)
{
    (void)in_sizes; (void)n_in; (void)out_size;
    const float* X  = (const float*)d_in[0];
    const float* Wq = (const float*)d_in[1];
    const float* bq = (const float*)d_in[2];
    const float* Wk = (const float*)d_in[3];
    const float* bk = (const float*)d_in[4];
    const float* Wv = (const float*)d_in[5];
    const float* bv = (const float*)d_in[6];
    float* out = (float*)d_out;

    cudaFuncSetAttribute(qkv_mma_kernel,
                         cudaFuncAttributeMaxDynamicSharedMemorySize, GSM_TOT);
    cudaFuncSetAttribute(attn_kernel,
                         cudaFuncAttributeMaxDynamicSharedMemorySize, SMTOT);

    conv_x_kernel<<<(B_ * S_ * 384) / 256, 256>>>(X);
    conv_w_kernel<<<dim3(KB_, H_ / 64, 3), 256>>>(Wq, Wk, Wv);
    qkv_mma_kernel<<<dim3(H_ / 256, (B_ * S_) / 128, 3), 512, GSM_TOT>>>(bq, bk, bv);
    attn_kernel<<<dim3(S_ / 128, NH_, B_), 128, SMTOT>>>(out);
}

// round 12
// speedup vs baseline: 2.7737x; 1.0586x over previous
#include <cuda_runtime.h>
#include <cuda_fp16.h>
#include <cstdint>

#define B_  2
#define S_  2048
#define H_  768
#define NH_ 12
#define HD_ 64
#define KB_ 12          // 768 / 64 k-chunks

// fp16 projections: [bh][s][64]. Q pre-scaled by log2(e)/8.
__device__ __align__(16) __half g_qh[(size_t)B_ * NH_ * S_ * 64];
__device__ __align__(16) __half g_kh[(size_t)B_ * NH_ * S_ * 64];
__device__ __align__(16) __half g_vh[(size_t)B_ * NH_ * S_ * 64];
// fp16 GEMM inputs:
__device__ __align__(16) __half g_xh[(size_t)B_ * S_ * KB_ * 64];
__device__ __align__(16) __half g_wh[(size_t)3 * H_ * KB_ * 64];

// ============================ PTX helpers ==================================
__device__ __forceinline__ uint32_t smem_u32(const void* p) {
    uint32_t a;
    asm("{ .reg .u64 t; cvta.to.shared.u64 t, %1; cvt.u32.u64 %0, t; }"
        : "=r"(a) : "l"(p));
    return a;
}
__device__ __forceinline__ void cpasync16(uint32_t dst, const void* src) {
    asm volatile("cp.async.cg.shared.global [%0], [%1], 16;"
                 :: "r"(dst), "l"(src) : "memory");
}
#define CP_COMMIT() asm volatile("cp.async.commit_group;" ::: "memory")
#define CP_WAIT0()  asm volatile("cp.async.wait_group 0;" ::: "memory")
#define CP_WAIT1()  asm volatile("cp.async.wait_group 1;" ::: "memory")
#define CP_WAIT2()  asm volatile("cp.async.wait_group 2;" ::: "memory")

__device__ __forceinline__ void ldsm4(uint32_t r[4], uint32_t addr) {
    asm volatile("ldmatrix.sync.aligned.m8n8.x4.shared.b16 {%0,%1,%2,%3}, [%4];"
        : "=r"(r[0]), "=r"(r[1]), "=r"(r[2]), "=r"(r[3]) : "r"(addr));
}
__device__ __forceinline__ void ldsm4t(uint32_t r[4], uint32_t addr) {
    asm volatile("ldmatrix.sync.aligned.m8n8.x4.trans.shared.b16 {%0,%1,%2,%3}, [%4];"
        : "=r"(r[0]), "=r"(r[1]), "=r"(r[2]), "=r"(r[3]) : "r"(addr));
}
// fp16 MMA, fp32 accumulate
__device__ __forceinline__ void mma16816h(float c[4], const uint32_t a[4],
                                          uint32_t b0, uint32_t b1) {
    asm volatile("mma.sync.aligned.m16n8k16.row.col.f32.f16.f16.f32 "
        "{%0,%1,%2,%3}, {%4,%5,%6,%7}, {%8,%9}, {%0,%1,%2,%3};"
        : "+f"(c[0]), "+f"(c[1]), "+f"(c[2]), "+f"(c[3])
        : "r"(a[0]), "r"(a[1]), "r"(a[2]), "r"(a[3]), "r"(b0), "r"(b1));
}
// pack two fp32 -> f16x2 (first arg -> bits [15:0])
__device__ __forceinline__ uint32_t packh(float lo, float hi) {
    uint32_t r; asm("cvt.rn.f16x2.f32 %0, %1, %2;" : "=r"(r) : "f"(hi), "f"(lo));
    return r;
}
// packed fp16x2 exp2
__device__ __forceinline__ uint32_t ex2h2(uint32_t x) {
    uint32_t y; asm("ex2.approx.f16x2 %0, %1;" : "=r"(y) : "r"(x)); return y;
}
// 128B rows (64 fp16), 8 chunks of 16B, XOR swizzle -> conflict-free ldmatrix
__device__ __forceinline__ uint32_t swa8(int row, int chunk) {
    return (uint32_t)(row * 128 + ((chunk ^ (row & 7)) << 4));
}

// ---------------------------------------------------------------------------
// Fused conversion kernel.
// blocks [0, 6144): conv_x  X fp32 [4096][768] -> g_xh fp16 [m][kb][64]
// blocks [6144, 6576): conv_w  W fp32 -> g_wh fp16 [which][n][kb][64] (transp)
// ---------------------------------------------------------------------------
#define CVX_BLOCKS 6144

__global__ __launch_bounds__(256) void conv_kernel(
    const float* __restrict__ X,
    const float* __restrict__ Wq, const float* __restrict__ Wk,
    const float* __restrict__ Wv)
{
    __shared__ float T[64][65];
    const int tid = threadIdx.x;

    if (blockIdx.x < CVX_BLOCKS) {
        const int t = blockIdx.x * 256 + tid;
        const int m = t / 384, r = t % 384;
        const int kb = r >> 5, pr = r & 31;
        float2 x = *(const float2*)(X + (size_t)m * H_ + kb * 64 + 2 * pr);
        uint32_t* dst = (uint32_t*)(g_xh + ((size_t)m * KB_ + kb) * 64);
        dst[pr] = packh(x.x, x.y);
        return;
    }

    const int i = blockIdx.x - CVX_BLOCKS;     // 432 blocks
    const int kb = i % KB_;
    const int ng = (i / KB_) % 12;
    const int which = i / (KB_ * 12);
    const float* W = (which == 0) ? Wq : (which == 1) ? Wk : Wv;

    #pragma unroll
    for (int j = 0; j < 16; j++) {
        int idx = tid + 256 * j;
        int r = idx >> 6, c = idx & 63;
        T[r][c] = W[(size_t)(kb * 64 + r) * H_ + ng * 64 + c];
    }
    __syncthreads();

    const int n  = tid >> 2;
    const int jb = tid & 3;
    uint32_t* dst = (uint32_t*)(g_wh +
        (((size_t)which * H_ + ng * 64 + n) * KB_ + kb) * 64);
    #pragma unroll
    for (int j = 0; j < 8; j++) {
        int k2 = jb * 8 + j;
        dst[k2] = packh(T[2 * k2][n], T[2 * k2 + 1][n]);
    }
}

// ---------------------------------------------------------------------------
// fp16 HMMA QKV GEMM: 256 thr (8 warps, 4m x 2n), tile 128m x 128n (2 heads),
// 64-k chunks triple-buffered. smem 3 x (A 16KB + B 16KB) = 96KB, 2 CTAs/SM.
// ---------------------------------------------------------------------------
#define GSM_TOT 98304
#define GBUF    32768

__global__ void __launch_bounds__(256, 2) qkv_mma_kernel(
    const float* __restrict__ bq, const float* __restrict__ bk,
    const float* __restrict__ bv)
{
    extern __shared__ char sm[];
    const uint32_t smb = smem_u32(sm);

    const int tid = threadIdx.x;
    const int l = tid & 31, w = tid >> 5;
    const int wm = w & 3, wn = w >> 2;           // 4 m-warps x 2 n-warps
    const int which = blockIdx.z;
    const int m0 = blockIdx.y * 128;
    const int n0 = blockIdx.x * 128;

    const __half* Ag = g_xh + (size_t)m0 * KB_ * 64;
    const __half* Bg = g_wh + ((size_t)which * H_ + n0) * KB_ * 64;

    float s[2][8][4];
    #pragma unroll
    for (int mt = 0; mt < 2; mt++)
        #pragma unroll
        for (int nt = 0; nt < 8; nt++)
            #pragma unroll
            for (int j = 0; j < 4; j++) s[mt][nt][j] = 0.0f;

    const int arow0 = 32 * wm + (l & 15);
    const int achnk = l >> 4;
    const int krow  = 64 * wn + (l & 7) + ((l >> 4) << 3);
    const int kchnk = (l >> 3) & 1;

    // prologue: chunks 0 and 1 into buffers 0 and 1
    #pragma unroll
    for (int pb = 0; pb < 2; pb++) {
        const uint32_t off = (uint32_t)(pb * GBUF);
        #pragma unroll
        for (int i = 0; i < 4; i++) {        // A: 128 rows x 8 chunks = 1024
            int idx = tid + 256 * i;
            int r = idx >> 3, ch = idx & 7;
            cpasync16(smb + off + swa8(r, ch),
                      Ag + ((size_t)r * KB_ + pb) * 64 + ch * 8);
        }
        #pragma unroll
        for (int i = 0; i < 4; i++) {        // B: 128 rows x 8 chunks = 1024
            int idx = tid + 256 * i;
            int r = idx >> 3, ch = idx & 7;
            cpasync16(smb + off + 16384 + swa8(r, ch),
                      Bg + ((size_t)r * KB_ + pb) * 64 + ch * 8);
        }
        CP_COMMIT();
    }

    for (int kb = 0; kb < KB_; kb++) {
        CP_WAIT1();
        __syncthreads();
        if (kb + 2 < KB_) {
            const uint32_t off = (uint32_t)(((kb + 2) % 3) * GBUF);
            #pragma unroll
            for (int i = 0; i < 4; i++) {
                int idx = tid + 256 * i;
                int r = idx >> 3, ch = idx & 7;
                cpasync16(smb + off + swa8(r, ch),
                          Ag + ((size_t)r * KB_ + kb + 2) * 64 + ch * 8);
            }
            #pragma unroll
            for (int i = 0; i < 4; i++) {
                int idx = tid + 256 * i;
                int r = idx >> 3, ch = idx & 7;
                cpasync16(smb + off + 16384 + swa8(r, ch),
                          Bg + ((size_t)r * KB_ + kb + 2) * 64 + ch * 8);
            }
        }
        CP_COMMIT();

        const uint32_t smA = smb + (uint32_t)((kb % 3) * GBUF);
        const uint32_t smB = smA + 16384;

        #pragma unroll
        for (int ks = 0; ks < 4; ks++) {
            uint32_t a[2][4], bb[4][4];
            #pragma unroll
            for (int mt = 0; mt < 2; mt++)
                ldsm4(a[mt], smA + swa8(arow0 + 16 * mt, ks * 2 + achnk));
            #pragma unroll
            for (int bt = 0; bt < 4; bt++)
                ldsm4(bb[bt], smB + swa8(16 * bt + krow, ks * 2 + kchnk));
            #pragma unroll
            for (int mt = 0; mt < 2; mt++)
                #pragma unroll
                for (int bt = 0; bt < 4; bt++) {
                    mma16816h(s[mt][2 * bt],     a[mt], bb[bt][0], bb[bt][1]);
                    mma16816h(s[mt][2 * bt + 1], a[mt], bb[bt][2], bb[bt][3]);
                }
        }
    }

    // ---- epilogue: +bias, (Q: *log2e/8), fp16 pack, store [bh][s][64] ----
    const float* bias = (which == 0) ? bq : (which == 1) ? bk : bv;
    __half* Gp = (which == 0) ? g_qh : (which == 1) ? g_kh : g_vh;
    const float sc = (which == 0) ? 0.18033688011112042f : 1.0f;

    const int head = 2 * blockIdx.x + wn;
    #pragma unroll
    for (int mt = 0; mt < 2; mt++) {
        const int r0 = m0 + 32 * wm + 16 * mt + (l >> 2);
        const int b  = r0 >> 11;
        const int s0 = r0 & (S_ - 1);
        const int bh_ = b * NH_ + head;
        uint32_t* d0 = (uint32_t*)(Gp + ((size_t)bh_ * S_ + s0) * 64);
        uint32_t* d1 = (uint32_t*)(Gp + ((size_t)bh_ * S_ + s0 + 8) * 64);
        #pragma unroll
        for (int nt = 0; nt < 8; nt++) {
            const int c0 = 8 * nt + 2 * (l & 3);
            const float b0 = __ldg(bias + head * 64 + c0);
            const float b1 = __ldg(bias + head * 64 + c0 + 1);
            d0[c0 >> 1] = packh((s[mt][nt][0] + b0) * sc, (s[mt][nt][1] + b1) * sc);
            d1[c0 >> 1] = packh((s[mt][nt][2] + b0) * sc, (s[mt][nt][3] + b1) * sc);
        }
    }
}

// ---------------------------------------------------------------------------
// fp16 HMMA flash attention v4: q-tile 128/CTA (2 sets of 64), kv-buffer 128
// processed as two 64-kv sub-steps (half the barriers of v3), K/V fragments
// shared across q-sets, f16x2 exp, row-sums via ones-MMA.
// smem: Q 16KB + 3 x 32KB = 112KB; 2 CTAs/SM.
// ---------------------------------------------------------------------------
#define SMQ   0
#define SMKV  16384
#define SMTOT 114688
#define NT_   (S_ / 128)

__global__ void __launch_bounds__(128, 2) attn_kernel(float* __restrict__ out)
{
    extern __shared__ char sm[];
    const uint32_t smb = smem_u32(sm);
    const uint32_t smq = smb + SMQ;

    const int tid = threadIdx.x;
    const int l = tid & 31, w = tid >> 5;
    const int head = blockIdx.y, b = blockIdx.z;
    const int bh = b * NH_ + head;
    const int q0 = blockIdx.x * 128;

    const __half* Kg0 = g_kh + (size_t)bh * S_ * 64;
    const __half* Vg0 = g_vh + (size_t)bh * S_ * 64;

    // --- prologue: Q (128 rows), kv-buffers 0 and 1 (128 kv rows each) ---
    {
        const __half* Qg = g_qh + ((size_t)bh * S_ + q0) * 64;
        #pragma unroll
        for (int i = 0; i < 8; i++) {
            int idx = tid + 128 * i;
            int r = idx >> 3, ch = idx & 7;
            cpasync16(smq + swa8(r, ch), Qg + (size_t)r * 64 + ch * 8);
        }
        CP_COMMIT();
    }
    #pragma unroll
    for (int pb = 0; pb < 2; pb++) {
        const uint32_t kvb = smb + SMKV + (uint32_t)(pb * 32768);
        const __half* Kg = Kg0 + (size_t)pb * 128 * 64;
        const __half* Vg = Vg0 + (size_t)pb * 128 * 64;
        #pragma unroll
        for (int i = 0; i < 8; i++) {
            int idx = tid + 128 * i;
            int r = idx >> 3, ch = idx & 7;     // r: 0..127
            uint32_t d = swa8(r, ch);
            cpasync16(kvb + d,         Kg + (size_t)r * 64 + ch * 8);
            cpasync16(kvb + 16384 + d, Vg + (size_t)r * 64 + ch * 8);
        }
        CP_COMMIT();
    }

    // fragment lane constants
    const int arow  = (w << 4) + (l & 15);
    const int achnk = l >> 4;
    const int krow  = (l & 7) + ((l >> 4) << 3);
    const int kchnk = (l >> 3) & 1;
    const int vchnk = l >> 4;
    const uint32_t ONES = 0x3C003C00u;   // fp16 (1.0, 1.0)

    // --- hoist Q fragments (both sets) into registers ---
    CP_WAIT2();
    __syncthreads();
    uint32_t qf[2][4][4];
    #pragma unroll
    for (int st = 0; st < 2; st++)
        #pragma unroll
        for (int ks = 0; ks < 4; ks++)
            ldsm4(qf[st][ks], smq + swa8(st * 64 + arow, ks * 2 + achnk));

    float o[2][8][4];
    #pragma unroll
    for (int st = 0; st < 2; st++)
        #pragma unroll
        for (int i = 0; i < 8; i++)
            #pragma unroll
            for (int j = 0; j < 4; j++) o[st][i][j] = 0.0f;
    float lacc[2][4];
    #pragma unroll
    for (int st = 0; st < 2; st++)
        #pragma unroll
        for (int j = 0; j < 4; j++) lacc[st][j] = 0.0f;

    for (int t = 0; t < NT_; t++) {
        CP_WAIT1();          // kv buffer t resident
        __syncthreads();     // all warps past compute(t-1)
        if (t + 2 < NT_) {
            const uint32_t kvb = smb + SMKV + (uint32_t)(((t + 2) % 3) * 32768);
            const __half* Kg = Kg0 + (size_t)(t + 2) * 128 * 64;
            const __half* Vg = Vg0 + (size_t)(t + 2) * 128 * 64;
            #pragma unroll
            for (int i = 0; i < 8; i++) {
                int idx = tid + 128 * i;
                int r = idx >> 3, ch = idx & 7;
                uint32_t d = swa8(r, ch);
                cpasync16(kvb + d,         Kg + (size_t)r * 64 + ch * 8);
                cpasync16(kvb + 16384 + d, Vg + (size_t)r * 64 + ch * 8);
            }
        }
        CP_COMMIT();

        const uint32_t kvb = smb + SMKV + (uint32_t)((t % 3) * 32768);

        #pragma unroll
        for (int sub = 0; sub < 2; sub++) {
            const uint32_t smk = kvb + (uint32_t)(sub * 8192);
            const uint32_t smv = kvb + 16384 + (uint32_t)(sub * 8192);

            // ---- S = Q.K^T for both q-sets, K fragments loaded once ----
            float s0[8][4], s1[8][4];
            #pragma unroll
            for (int i = 0; i < 8; i++)
                #pragma unroll
                for (int j = 0; j < 4; j++) { s0[i][j] = 0.0f; s1[i][j] = 0.0f; }

            #pragma unroll
            for (int ks = 0; ks < 4; ks++) {
                #pragma unroll
                for (int np = 0; np < 4; np++) {
                    uint32_t kk[4];
                    ldsm4(kk, smk + swa8(np * 16 + krow, ks * 2 + kchnk));
                    mma16816h(s0[2 * np],     qf[0][ks], kk[0], kk[1]);
                    mma16816h(s0[2 * np + 1], qf[0][ks], kk[2], kk[3]);
                    mma16816h(s1[2 * np],     qf[1][ks], kk[0], kk[1]);
                    mma16816h(s1[2 * np + 1], qf[1][ks], kk[2], kk[3]);
                }
            }

            // ---- exp2 (f16x2), row-sums via ones-MMA, PV shared V frags ----
            #pragma unroll
            for (int c = 0; c < 4; c++) {
                uint32_t a0[4], a1[4];
                #pragma unroll
                for (int h = 0; h < 2; h++) {
                    float* p0 = s0[2 * c + h];
                    float* p1 = s1[2 * c + h];
                    a0[2 * h]     = ex2h2(packh(p0[0], p0[1]));
                    a0[2 * h + 1] = ex2h2(packh(p0[2], p0[3]));
                    a1[2 * h]     = ex2h2(packh(p1[0], p1[1]));
                    a1[2 * h + 1] = ex2h2(packh(p1[2], p1[3]));
                }
                mma16816h(lacc[0], a0, ONES, ONES);
                mma16816h(lacc[1], a1, ONES, ONES);

                const int vrow = c * 16 + (l & 15);
                #pragma unroll
                for (int j = 0; j < 4; j++) {
                    uint32_t vv[4];
                    ldsm4t(vv, smv + swa8(vrow, 2 * j + vchnk));
                    mma16816h(o[0][2 * j],     a0, vv[0], vv[1]);
                    mma16816h(o[0][2 * j + 1], a0, vv[2], vv[3]);
                    mma16816h(o[1][2 * j],     a1, vv[0], vv[1]);
                    mma16816h(o[1][2 * j + 1], a1, vv[2], vv[3]);
                }
            }
        }
    }

    // ---- epilogue: ones-MMA already produced complete row sums ----
    const int colb = head * HD_ + 2 * (l & 3);
    #pragma unroll
    for (int st = 0; st < 2; st++) {
        const float inv0 = 1.0f / lacc[st][0];
        const float inv1 = 1.0f / lacc[st][2];
        const int row0 = q0 + st * 64 + w * 16 + (l >> 2);
        const int row1 = row0 + 8;
        float* out0 = out + ((size_t)b * S_ + row0) * H_ + colb;
        float* out1 = out + ((size_t)b * S_ + row1) * H_ + colb;
        #pragma unroll
        for (int nt = 0; nt < 8; nt++) {
            *(float2*)(out0 + nt * 8) =
                make_float2(o[st][nt][0] * inv0, o[st][nt][1] * inv0);
            *(float2*)(out1 + nt * 8) =
                make_float2(o[st][nt][2] * inv1, o[st][nt][3] * inv1);
        }
    }
}

// ---------------------------------------------------------------------------
extern "C" void kernel_launch(void* const* d_in, const int* in_sizes, int n_in,
                              void* d_out, int out_size)
{
    (void)in_sizes; (void)n_in; (void)out_size;
    const float* X  = (const float*)d_in[0];
    const float* Wq = (const float*)d_in[1];
    const float* bq = (const float*)d_in[2];
    const float* Wk = (const float*)d_in[3];
    const float* bk = (const float*)d_in[4];
    const float* Wv = (const float*)d_in[5];
    const float* bv = (const float*)d_in[6];
    float* out = (float*)d_out;

    cudaFuncSetAttribute(qkv_mma_kernel,
                         cudaFuncAttributeMaxDynamicSharedMemorySize, GSM_TOT);
    cudaFuncSetAttribute(attn_kernel,
                         cudaFuncAttributeMaxDynamicSharedMemorySize, SMTOT);

    conv_kernel<<<CVX_BLOCKS + 3 * 12 * KB_, 256>>>(X, Wq, Wk, Wv);
    qkv_mma_kernel<<<dim3(H_ / 128, (B_ * S_) / 128, 3), 256, GSM_TOT>>>(bq, bk, bv);
    attn_kernel<<<dim3(S_ / 128, NH_, B_), 128, SMTOT>>>(out);
}